// round 7
// baseline (speedup 1.0000x reference)
#include <cuda_runtime.h>
#include <cstdint>

#define BB 4
#define HH 48
#define WW 48
#define CC 128

typedef unsigned long long u64;

// ---------------- scratch (device globals; no allocation allowed) ----------
__device__ float g_F [BB*HH*WW*CC];      // raw features, pixel-major
__device__ float g_FN[BB*HH*WW*CC];      // layernormed features, pixel-major
__device__ float g_Q [BB*HH*WW*CC];      // queries per pixel
__device__ float g_KV[BB*HH*WW*256];     // per-pixel KV projection (K|V)
__device__ float g_KVmid[BB*24*24*256];  // 2x2 pooled KV
__device__ float g_KVglo[BB*12*12*256];  // 4x4 pooled KV

__device__ __forceinline__ float ex2f(float x) {
    float r; asm("ex2.approx.f32 %0, %1;" : "=f"(r) : "f"(x)); return r;
}
__device__ __forceinline__ u64 ffma2(u64 a, u64 b, u64 c) {
    u64 d; asm("fma.rn.f32x2 %0,%1,%2,%3;" : "=l"(d) : "l"(a), "l"(b), "l"(c)); return d;
}
__device__ __forceinline__ u64 fmul2(u64 a, u64 b) {
    u64 d; asm("mul.rn.f32x2 %0,%1,%2;" : "=l"(d) : "l"(a), "l"(b)); return d;
}
__device__ __forceinline__ u64 pk2(float lo, float hi) {
    u64 d; asm("mov.b64 %0,{%1,%2};" : "=l"(d) : "f"(lo), "f"(hi)); return d;
}
__device__ __forceinline__ void up2(u64 v, float& lo, float& hi) {
    asm("mov.b64 {%0,%1},%2;" : "=f"(lo), "=f"(hi) : "l"(v));
}
__device__ __forceinline__ void cp16(uint32_t dst, const float* src) {
    asm volatile("cp.async.cg.shared.global [%0], [%1], 16;" :: "r"(dst), "l"(src));
}

// ============================================================================
// Kernel 0: transpose NCHW -> pixel-major + LayerNorm.  One warp per pixel.
// (known-good R5 version)
// ============================================================================
__global__ void k0_ln(const float* __restrict__ feat,
                      const float* __restrict__ lnw,
                      const float* __restrict__ lnb) {
    int warp = (blockIdx.x * blockDim.x + threadIdx.x) >> 5;
    int lane = threadIdx.x & 31;
    if (warp >= BB*HH*WW) return;
    int b   = warp / (HH*WW);
    int rem = warp % (HH*WW);
    const float* src = feat + (size_t)b * CC * HH * WW + rem;

    float v[4];
    float s = 0.f, ss = 0.f;
#pragma unroll
    for (int i = 0; i < 4; i++) {
        int c = lane + 32*i;
        v[i] = src[(size_t)c * (HH*WW)];
        s  += v[i];
        ss += v[i]*v[i];
    }
#pragma unroll
    for (int o = 16; o; o >>= 1) {
        s  += __shfl_xor_sync(0xffffffffu, s,  o);
        ss += __shfl_xor_sync(0xffffffffu, ss, o);
    }
    float mean = s * (1.f/128.f);
    float var  = ss * (1.f/128.f) - mean*mean;
    float rstd = rsqrtf(var + 1e-5f);

    float* dF = g_F  + (size_t)warp * CC;
    float* dN = g_FN + (size_t)warp * CC;
#pragma unroll
    for (int i = 0; i < 4; i++) {
        int c = lane + 32*i;
        dF[c] = v[i];
        dN[c] = (v[i] - mean) * rstd * lnw[c] + lnb[c];
    }
}

// ============================================================================
// Kernel 1: fused GEMMs (Q / K / V projections).  (known-good R5 version)
// ============================================================================
#define MT 64
#define PADK 36

__global__ void k1_gemm(const float* __restrict__ qw, const float* __restrict__ qb,
                        const float* __restrict__ kvw, const float* __restrict__ kvb) {
    __shared__ float sA[MT][PADK];
    __shared__ float sB[128][PADK];

    int sub   = blockIdx.y;
    int mBase = blockIdx.x * MT;
    const float* A    = (sub == 0) ? g_FN : g_F;
    const float* Wm   = (sub == 0) ? qw : (kvw + (size_t)(sub-1)*128*128);
    const float* bias = (sub == 0) ? qb : (kvb + (sub-1)*128);

    int tid = threadIdx.x;
    int mg = tid & 15;
    int ng = tid >> 4;

    float acc[4][8];
#pragma unroll
    for (int m = 0; m < 4; m++)
#pragma unroll
        for (int n = 0; n < 8; n++) acc[m][n] = 0.f;

    for (int ck = 0; ck < 4; ck++) {
        __syncthreads();
#pragma unroll
        for (int i = 0; i < 2; i++) {
            int f = tid + i*256;
            int pix = f >> 3, kq = f & 7;
            float4 val = *(const float4*)(A + (size_t)(mBase+pix)*128 + ck*32 + kq*4);
            *(float4*)&sA[pix][kq*4] = val;
        }
#pragma unroll
        for (int i = 0; i < 4; i++) {
            int f = tid + i*256;
            int row = f >> 3, kq = f & 7;
            float4 val = *(const float4*)(Wm + (size_t)row*128 + ck*32 + kq*4);
            *(float4*)&sB[row][kq*4] = val;
        }
        __syncthreads();

#pragma unroll
        for (int k4 = 0; k4 < 8; k4++) {
            float4 a0 = *(const float4*)&sA[mg*4+0][k4*4];
            float4 a1 = *(const float4*)&sA[mg*4+1][k4*4];
            float4 a2 = *(const float4*)&sA[mg*4+2][k4*4];
            float4 a3 = *(const float4*)&sA[mg*4+3][k4*4];
#pragma unroll
            for (int n = 0; n < 8; n++) {
                float4 bv = *(const float4*)&sB[ng*8+n][k4*4];
                acc[0][n] += a0.x*bv.x + a0.y*bv.y + a0.z*bv.z + a0.w*bv.w;
                acc[1][n] += a1.x*bv.x + a1.y*bv.y + a1.z*bv.z + a1.w*bv.w;
                acc[2][n] += a2.x*bv.x + a2.y*bv.y + a2.z*bv.z + a2.w*bv.w;
                acc[3][n] += a3.x*bv.x + a3.y*bv.y + a3.z*bv.z + a3.w*bv.w;
            }
        }
    }

    float4 bv0 = *(const float4*)(bias + ng*8);
    float4 bv1 = *(const float4*)(bias + ng*8 + 4);
    int stride = (sub == 0) ? 128 : 256;
    float* base = (sub == 0) ? (g_Q + ng*8) : (g_KV + (sub-1)*128 + ng*8);
#pragma unroll
    for (int m = 0; m < 4; m++) {
        float* dst = base + (size_t)(mBase + mg*4 + m) * stride;
        float4 r0 = make_float4(acc[m][0]+bv0.x, acc[m][1]+bv0.y, acc[m][2]+bv0.z, acc[m][3]+bv0.w);
        float4 r1 = make_float4(acc[m][4]+bv1.x, acc[m][5]+bv1.y, acc[m][6]+bv1.z, acc[m][7]+bv1.w);
        *(float4*)dst       = r0;
        *((float4*)dst + 1) = r1;
    }
}

// ============================================================================
// Kernel 2: pooled KV.  Unchanged.
// ============================================================================
__global__ void k2_pool() {
    int t = blockIdx.x;
    int c = threadIdx.x;
    if (t < BB*576) {
        int b = t / 576, r = t % 576, my = r / 24, mx = r % 24;
        const float* base = g_KV + ((size_t)((b*48 + my*2)*48 + mx*2))*256 + c;
        float v = base[0] + base[256] + base[48*256] + base[48*256 + 256];
        g_KVmid[(size_t)t*256 + c] = v * 0.25f;
    } else {
        int t2 = t - BB*576;
        int b = t2 / 144, r = t2 % 144, gy = r / 12, gx = r % 12;
        float v = 0.f;
#pragma unroll
        for (int i = 0; i < 4; i++)
#pragma unroll
            for (int j = 0; j < 4; j++)
                v += g_KV[((size_t)((b*48 + gy*4 + i)*48 + gx*4 + j))*256 + c];
        g_KVglo[(size_t)t2*256 + c] = v * (1.f/16.f);
    }
}

// ============================================================================
// Kernel 3 v6: 2x2 window group.
//   16 slots of 64 rows, double-buffered cp.async ring (2 x 64 KB):
//     slots 0..3  = local subtiles (4 windows x 16 tokens each); compute is
//                   j-split across halves (th0: j 0-7, th1: j 8-15) -> no
//                   masks, no double count, all warps active.
//     slots 4..15 = mid/glo chunks of 64 tokens; row-split (th0: 0-31,
//                   th1: 32-63).
//   Lane owns 2 queries (lane -> windows {0,1}, lane+32 -> {2,3}); partials
//   merged via smem; fused out-projection epilogue (R5, known good).
// ============================================================================
#define NSLOT 16

__global__ void __launch_bounds__(512, 1)
k3_attn(const float* __restrict__ feat, const float* __restrict__ kvb,
        const float* __restrict__ ow,   const float* __restrict__ ob,
        float* __restrict__ out) {
    extern __shared__ float ds[];     // 131072 B: ring[2][64][256]

    int cta = blockIdx.x;
    int b = cta / 36, g = cta % 36;
    int gy = g / 6, gx = g % 6;
    int tid  = threadIdx.x;
    int lane = tid & 31;
    int warp = tid >> 5;
    int h = warp & 7, th = warp >> 3;

    int qg0 = lane, qg1 = lane + 32;
    int wgA = qg0 >> 4, wgB = qg1 >> 4;     // wgA in {0,1}, wgB in {2,3}

    const float SC = 0.25f * 1.4426950408889634f;
    u64 SC2 = pk2(SC, SC);

    // ---- load 2 queries (16 dims each), pre-scaled ----
    u64 q0[8], q1[8];
    {
        int qi = qg0 & 15;
        int wy = gy*2 + (wgA>>1), wx = gx*2 + (wgA&1);
        int py = wy*4 + (qi>>2), px = wx*4 + (qi&3);
        const longlong2* qp = (const longlong2*)(g_Q + ((size_t)((b*48+py)*48+px))*128 + h*16);
#pragma unroll
        for (int i = 0; i < 4; i++) {
            longlong2 t2 = qp[i];
            q0[2*i]   = fmul2((u64)t2.x, SC2);
            q0[2*i+1] = fmul2((u64)t2.y, SC2);
        }
    }
    {
        int qi = qg1 & 15;
        int wy = gy*2 + (wgB>>1), wx = gx*2 + (wgB&1);
        int py = wy*4 + (qi>>2), px = wx*4 + (qi&3);
        const longlong2* qp = (const longlong2*)(g_Q + ((size_t)((b*48+py)*48+px))*128 + h*16);
#pragma unroll
        for (int i = 0; i < 4; i++) {
            longlong2 t2 = qp[i];
            q1[2*i]   = fmul2((u64)t2.x, SC2);
            q1[2*i+1] = fmul2((u64)t2.y, SC2);
        }
    }

    u64 acc0[8], acc1[8];
#pragma unroll
    for (int i = 0; i < 8; i++) { acc0[i] = 0ull; acc1[i] = 0ull; }
    float ls0 = 0.f, ls1 = 0.f;

    // staging map: 64 rows, 8 threads/row, 32 floats (8x cp16) each
    int srow = tid >> 3;
    int scol = (tid & 7) * 32;

    // stage slot s (0..15) into ring buffer s&1
    auto stage = [&](int s) {
        const float* src;
        if (s < 4) {                         // local subtile s
            int w2 = srow >> 4, j = srow & 15;
            int idx = s*16 + j;
            int y = (gy*2 + (w2>>1))*4 + (idx>>3) - 2;
            int x = (gx*2 + (w2&1))*4  + (idx&7)  - 2;
            src = ((unsigned)y < 48u && (unsigned)x < 48u)
                ? (g_KV + ((size_t)((b*48+y)*48+x))*256) : kvb;
        } else {                             // mid/glo chunk s-4
            int tk = (s-4)*64 + srow;
            if (tk < 576)      src = g_KVmid + ((size_t)(b*576 + tk))*256;
            else if (tk < 720) src = g_KVglo + ((size_t)(b*144 + tk-576))*256;
            else               src = kvb;    // padding rows (unread)
        }
        uint32_t dst = (uint32_t)__cvta_generic_to_shared(ds + (s&1)*16384 + srow*256 + scol);
#pragma unroll
        for (int i = 0; i < 8; i++) cp16(dst + i*16, src + scol + i*4);
        asm volatile("cp.async.commit_group;");
    };

    stage(0);

    for (int s = 0; s < NSLOT; s++) {
        if (s + 1 < NSLOT) {
            stage(s+1);
            asm volatile("cp.async.wait_group 1;");
        } else {
            asm volatile("cp.async.wait_group 0;");
        }
        __syncthreads();

        const float* buf = ds + (s&1)*16384;
        const float *kA, *kB;
        int n;
        if (s < 4) {           // local: query-specific window rows, j-split
            n = 8;
            kA = buf + (wgA*16 + th*8)*256 + h*16;
            kB = buf + (wgB*16 + th*8)*256 + h*16;
        } else {               // mid/glo: shared rows, row-split
            n = ((s == NSLOT-1) ? 16 : 64) >> 1;
            kA = buf + (th*n)*256 + h*16;
            kB = kA;
        }

#pragma unroll 4
        for (int j = 0; j < n; j++) {
            const longlong2* kp0 = (const longlong2*)(kA + j*256);
            longlong2 a0 = kp0[0], a1 = kp0[1], a2 = kp0[2], a3 = kp0[3];

            u64 d0 = fmul2(q0[0], (u64)a0.x);
            d0 = ffma2(q0[1], (u64)a0.y, d0);
            d0 = ffma2(q0[2], (u64)a1.x, d0);
            d0 = ffma2(q0[3], (u64)a1.y, d0);
            d0 = ffma2(q0[4], (u64)a2.x, d0);
            d0 = ffma2(q0[5], (u64)a2.y, d0);
            d0 = ffma2(q0[6], (u64)a3.x, d0);
            d0 = ffma2(q0[7], (u64)a3.y, d0);

            const longlong2* kp1 = (const longlong2*)(kB + j*256);
            longlong2 c0 = kp1[0], c1 = kp1[1], c2 = kp1[2], c3 = kp1[3];
            u64 d1 = fmul2(q1[0], (u64)c0.x);
            d1 = ffma2(q1[1], (u64)c0.y, d1);
            d1 = ffma2(q1[2], (u64)c1.x, d1);
            d1 = ffma2(q1[3], (u64)c1.y, d1);
            d1 = ffma2(q1[4], (u64)c2.x, d1);
            d1 = ffma2(q1[5], (u64)c2.y, d1);
            d1 = ffma2(q1[6], (u64)c3.x, d1);
            d1 = ffma2(q1[7], (u64)c3.y, d1);

            float a, bb;
            up2(d0, a, bb); float p0 = ex2f(a + bb);
            up2(d1, a, bb); float p1 = ex2f(a + bb);
            ls0 += p0; ls1 += p1;
            u64 P0 = pk2(p0, p0), P1 = pk2(p1, p1);

            const longlong2* vp0 = (const longlong2*)(kA + j*256 + 128);
            longlong2 v0 = vp0[0], v1 = vp0[1], v2 = vp0[2], v3 = vp0[3];
            acc0[0] = ffma2(P0, (u64)v0.x, acc0[0]);
            acc0[1] = ffma2(P0, (u64)v0.y, acc0[1]);
            acc0[2] = ffma2(P0, (u64)v1.x, acc0[2]);
            acc0[3] = ffma2(P0, (u64)v1.y, acc0[3]);
            acc0[4] = ffma2(P0, (u64)v2.x, acc0[4]);
            acc0[5] = ffma2(P0, (u64)v2.y, acc0[5]);
            acc0[6] = ffma2(P0, (u64)v3.x, acc0[6]);
            acc0[7] = ffma2(P0, (u64)v3.y, acc0[7]);

            const longlong2* vp1 = (const longlong2*)(kB + j*256 + 128);
            longlong2 w0 = vp1[0], w1 = vp1[1], w2v = vp1[2], w3 = vp1[3];
            acc1[0] = ffma2(P1, (u64)w0.x,  acc1[0]);
            acc1[1] = ffma2(P1, (u64)w0.y,  acc1[1]);
            acc1[2] = ffma2(P1, (u64)w1.x,  acc1[2]);
            acc1[3] = ffma2(P1, (u64)w1.y,  acc1[3]);
            acc1[4] = ffma2(P1, (u64)w2v.x, acc1[4]);
            acc1[5] = ffma2(P1, (u64)w2v.y, acc1[5]);
            acc1[6] = ffma2(P1, (u64)w3.x,  acc1[6]);
            acc1[7] = ffma2(P1, (u64)w3.y,  acc1[7]);
        }
        __syncthreads();
    }

    // ------------------- merge halves, normalize, epilogue -----------------
    float* att = ds;                    // [64][132]
    float* lsm = ds + 64*132;           // [64][8]
    float* wsm = ds + 64*132 + 64*8;    // [16][132]

    if (th == 0) {
        float* r0 = &att[qg0*132 + h*16];
        float* r1 = &att[qg1*132 + h*16];
#pragma unroll
        for (int i = 0; i < 8; i++) {
            float a, bb;
            up2(acc0[i], a, bb); r0[2*i] = a; r0[2*i+1] = bb;
            up2(acc1[i], a, bb); r1[2*i] = a; r1[2*i+1] = bb;
        }
        lsm[qg0*8 + h] = ls0;
        lsm[qg1*8 + h] = ls1;
    }
    __syncthreads();
    if (th == 1) {
        float inv0 = 1.f / (lsm[qg0*8 + h] + ls0);
        float inv1 = 1.f / (lsm[qg1*8 + h] + ls1);
        float* r0 = &att[qg0*132 + h*16];
        float* r1 = &att[qg1*132 + h*16];
#pragma unroll
        for (int i = 0; i < 8; i++) {
            float a, bb;
            up2(acc0[i], a, bb);
            r0[2*i]   = (r0[2*i]   + a ) * inv0;
            r0[2*i+1] = (r0[2*i+1] + bb) * inv0;
            up2(acc1[i], a, bb);
            r1[2*i]   = (r1[2*i]   + a ) * inv1;
            r1[2*i+1] = (r1[2*i+1] + bb) * inv1;
        }
    }
    __syncthreads();

    // out projection: thread = (aqi = tid>>3, og = tid&7)
    int aqi = tid >> 3, og = tid & 7;
    float o[16];
#pragma unroll 1
    for (int ch = 0; ch < 8; ch++) {
        {
            int row = tid >> 5, quad = tid & 31;
            *(float4*)&wsm[row*132 + quad*4] =
                *(const float4*)(ow + (size_t)(ch*16 + row)*128 + quad*4);
        }
        __syncthreads();
        u64 r0p = 0ull, r1p = 0ull;
#pragma unroll
        for (int k4 = 0; k4 < 32; k4++) {
            longlong2 av = *(const longlong2*)&att[aqi*132 + k4*4];
            longlong2 w0 = *(const longlong2*)&wsm[og*132 + k4*4];
            longlong2 w1 = *(const longlong2*)&wsm[(og+8)*132 + k4*4];
            r0p = ffma2((u64)av.x, (u64)w0.x, r0p);
            r0p = ffma2((u64)av.y, (u64)w0.y, r0p);
            r1p = ffma2((u64)av.x, (u64)w1.x, r1p);
            r1p = ffma2((u64)av.y, (u64)w1.y, r1p);
        }
        float a, bb;
        up2(r0p, a, bb); o[ch*2]   = a + bb;
        up2(r1p, a, bb); o[ch*2+1] = a + bb;
        __syncthreads();
    }

    // residual add + NCHW scatter store
    {
        int qi = aqi & 15, wq = aqi >> 4;
        int wy = gy*2 + (wq>>1), wx = gx*2 + (wq&1);
        int py = wy*4 + (qi>>2), px = wx*4 + (qi&3);
#pragma unroll
        for (int ch = 0; ch < 8; ch++) {
#pragma unroll
            for (int u2 = 0; u2 < 2; u2++) {
                int oc = ch*16 + u2*8 + og;
                size_t gi = (((size_t)b*128 + oc)*48 + py)*48 + px;
                out[gi] = o[ch*2+u2] + ob[oc] + feat[gi];
            }
        }
    }
}

// ============================================================================
extern "C" void kernel_launch(void* const* d_in, const int* in_sizes, int n_in,
                              void* d_out, int out_size) {
    const float* feat = (const float*)d_in[0];
    const float* lnw  = (const float*)d_in[1];
    const float* lnb  = (const float*)d_in[2];
    const float* qw   = (const float*)d_in[3];
    const float* qb   = (const float*)d_in[4];
    const float* kvw  = (const float*)d_in[5];
    const float* kvb  = (const float*)d_in[6];
    const float* ow   = (const float*)d_in[7];
    const float* ob   = (const float*)d_in[8];
    float* out = (float*)d_out;

    cudaFuncSetAttribute(k3_attn, cudaFuncAttributeMaxDynamicSharedMemorySize, 131072);

    k0_ln<<<1152, 256>>>(feat, lnw, lnb);
    k1_gemm<<<dim3(144, 3), 256>>>(qw, qb, kvw, kvb);
    k2_pool<<<2880, 256>>>();
    k3_attn<<<144, 512, 131072>>>(feat, kvb, ow, ob, out);
}

// round 8
// speedup vs baseline: 1.2915x; 1.2915x over previous
#include <cuda_runtime.h>
#include <cstdint>

// Problem constants
#define BB 4
#define HH 48
#define WW 48
#define CC 128
#define NWIN 144
#define NHEAD 8

typedef unsigned long long u64;

// ---------------- scratch (device globals; no allocation allowed) ----------
__device__ float g_F [BB*HH*WW*CC];      // raw features, pixel-major
__device__ float g_FN[BB*HH*WW*CC];      // layernormed features, pixel-major
__device__ float g_Q [BB*HH*WW*CC];      // queries per pixel
__device__ float g_KV[BB*HH*WW*256];     // per-pixel KV projection (K|V)
__device__ float g_KVmid[BB*24*24*256];  // 2x2 pooled KV
__device__ float g_KVglo[BB*12*12*256];  // 4x4 pooled KV

__device__ __forceinline__ float ex2f(float x) {
    float r; asm("ex2.approx.f32 %0, %1;" : "=f"(r) : "f"(x)); return r;
}
__device__ __forceinline__ u64 ffma2(u64 a, u64 b, u64 c) {
    u64 d; asm("fma.rn.f32x2 %0,%1,%2,%3;" : "=l"(d) : "l"(a), "l"(b), "l"(c)); return d;
}
__device__ __forceinline__ u64 fmul2(u64 a, u64 b) {
    u64 d; asm("mul.rn.f32x2 %0,%1,%2;" : "=l"(d) : "l"(a), "l"(b)); return d;
}
__device__ __forceinline__ u64 pk2(float lo, float hi) {
    u64 d; asm("mov.b64 %0,{%1,%2};" : "=l"(d) : "f"(lo), "f"(hi)); return d;
}
__device__ __forceinline__ void up2(u64 v, float& lo, float& hi) {
    asm("mov.b64 {%0,%1},%2;" : "=f"(lo), "=f"(hi) : "l"(v));
}
__device__ __forceinline__ void cp16(uint32_t dst, const float* src) {
    asm volatile("cp.async.cg.shared.global [%0], [%1], 16;" :: "r"(dst), "l"(src));
}

// ============================================================================
// Kernel 0: transpose NCHW -> pixel-major + LayerNorm.  One warp per pixel.
// ============================================================================
__global__ void k0_ln(const float* __restrict__ feat,
                      const float* __restrict__ lnw,
                      const float* __restrict__ lnb) {
    int warp = (blockIdx.x * blockDim.x + threadIdx.x) >> 5;
    int lane = threadIdx.x & 31;
    if (warp >= BB*HH*WW) return;
    int b   = warp / (HH*WW);
    int rem = warp % (HH*WW);
    const float* src = feat + (size_t)b * CC * HH * WW + rem;

    float v[4];
    float s = 0.f, ss = 0.f;
#pragma unroll
    for (int i = 0; i < 4; i++) {
        int c = lane + 32*i;
        v[i] = src[(size_t)c * (HH*WW)];
        s  += v[i];
        ss += v[i]*v[i];
    }
#pragma unroll
    for (int o = 16; o; o >>= 1) {
        s  += __shfl_xor_sync(0xffffffffu, s,  o);
        ss += __shfl_xor_sync(0xffffffffu, ss, o);
    }
    float mean = s * (1.f/128.f);
    float var  = ss * (1.f/128.f) - mean*mean;
    float rstd = rsqrtf(var + 1e-5f);

    float* dF = g_F  + (size_t)warp * CC;
    float* dN = g_FN + (size_t)warp * CC;
#pragma unroll
    for (int i = 0; i < 4; i++) {
        int c = lane + 32*i;
        dF[c] = v[i];
        dN[c] = (v[i] - mean) * rstd * lnw[c] + lnb[c];
    }
}

// ============================================================================
// Kernel 1: fused GEMMs (Q / K / V projections).  Unchanged (known good).
// ============================================================================
#define MT 64
#define PADK 36

__global__ void k1_gemm(const float* __restrict__ qw, const float* __restrict__ qb,
                        const float* __restrict__ kvw, const float* __restrict__ kvb) {
    __shared__ float sA[MT][PADK];
    __shared__ float sB[128][PADK];

    int sub   = blockIdx.y;
    int mBase = blockIdx.x * MT;
    const float* A    = (sub == 0) ? g_FN : g_F;
    const float* Wm   = (sub == 0) ? qw : (kvw + (size_t)(sub-1)*128*128);
    const float* bias = (sub == 0) ? qb : (kvb + (sub-1)*128);

    int tid = threadIdx.x;
    int mg = tid & 15;
    int ng = tid >> 4;

    float acc[4][8];
#pragma unroll
    for (int m = 0; m < 4; m++)
#pragma unroll
        for (int n = 0; n < 8; n++) acc[m][n] = 0.f;

    for (int ck = 0; ck < 4; ck++) {
        __syncthreads();
#pragma unroll
        for (int i = 0; i < 2; i++) {
            int f = tid + i*256;
            int pix = f >> 3, kq = f & 7;
            float4 val = *(const float4*)(A + (size_t)(mBase+pix)*128 + ck*32 + kq*4);
            *(float4*)&sA[pix][kq*4] = val;
        }
#pragma unroll
        for (int i = 0; i < 4; i++) {
            int f = tid + i*256;
            int row = f >> 3, kq = f & 7;
            float4 val = *(const float4*)(Wm + (size_t)row*128 + ck*32 + kq*4);
            *(float4*)&sB[row][kq*4] = val;
        }
        __syncthreads();

#pragma unroll
        for (int k4 = 0; k4 < 8; k4++) {
            float4 a0 = *(const float4*)&sA[mg*4+0][k4*4];
            float4 a1 = *(const float4*)&sA[mg*4+1][k4*4];
            float4 a2 = *(const float4*)&sA[mg*4+2][k4*4];
            float4 a3 = *(const float4*)&sA[mg*4+3][k4*4];
#pragma unroll
            for (int n = 0; n < 8; n++) {
                float4 bv = *(const float4*)&sB[ng*8+n][k4*4];
                acc[0][n] += a0.x*bv.x + a0.y*bv.y + a0.z*bv.z + a0.w*bv.w;
                acc[1][n] += a1.x*bv.x + a1.y*bv.y + a1.z*bv.z + a1.w*bv.w;
                acc[2][n] += a2.x*bv.x + a2.y*bv.y + a2.z*bv.z + a2.w*bv.w;
                acc[3][n] += a3.x*bv.x + a3.y*bv.y + a3.z*bv.z + a3.w*bv.w;
            }
        }
    }

    float4 bv0 = *(const float4*)(bias + ng*8);
    float4 bv1 = *(const float4*)(bias + ng*8 + 4);
    int stride = (sub == 0) ? 128 : 256;
    float* base = (sub == 0) ? (g_Q + ng*8) : (g_KV + (sub-1)*128 + ng*8);
#pragma unroll
    for (int m = 0; m < 4; m++) {
        float* dst = base + (size_t)(mBase + mg*4 + m) * stride;
        float4 r0 = make_float4(acc[m][0]+bv0.x, acc[m][1]+bv0.y, acc[m][2]+bv0.z, acc[m][3]+bv0.w);
        float4 r1 = make_float4(acc[m][4]+bv1.x, acc[m][5]+bv1.y, acc[m][6]+bv1.z, acc[m][7]+bv1.w);
        *(float4*)dst       = r0;
        *((float4*)dst + 1) = r1;
    }
}

// ============================================================================
// Kernel 2: pooled KV.  Unchanged.
// ============================================================================
__global__ void k2_pool() {
    int t = blockIdx.x;
    int c = threadIdx.x;
    if (t < BB*576) {
        int b = t / 576, r = t % 576, my = r / 24, mx = r % 24;
        const float* base = g_KV + ((size_t)((b*48 + my*2)*48 + mx*2))*256 + c;
        float v = base[0] + base[256] + base[48*256] + base[48*256 + 256];
        g_KVmid[(size_t)t*256 + c] = v * 0.25f;
    } else {
        int t2 = t - BB*576;
        int b = t2 / 144, r = t2 % 144, gy = r / 12, gx = r % 12;
        float v = 0.f;
#pragma unroll
        for (int i = 0; i < 4; i++)
#pragma unroll
            for (int j = 0; j < 4; j++)
                v += g_KV[((size_t)((b*48 + gy*4 + i)*48 + gx*4 + j))*256 + c];
        g_KVglo[(size_t)t2*256 + c] = v * (1.f/16.f);
    }
}

// ============================================================================
// Kernel 3 v7 (= R5 structure + row-split scheduling):
//   16-row tiles, double-buffered cp.async ring (as R5 — known good).
//   CHANGE vs R5: every tile computed by ALL 16 warps, rows split
//   th0 -> j 0..7, th1 -> j 8..15 (no idle alternation).  Local tiles
//   (t<16, window wgl=t>>2) compute only the matching query path:
//   wgl<2 -> q0 (with lane mask), wgl>=2 -> q1.  Merge adds halves
//   (disjoint rows -> each token counted once).
// ============================================================================
#define NTILE 61

__global__ void __launch_bounds__(512, 1)
k3_attn(const float* __restrict__ feat, const float* __restrict__ kvb,
        const float* __restrict__ ow,   const float* __restrict__ ob,
        float* __restrict__ out) {
    __shared__ union {
        float kv[2][16][256];                        // 32 KB (mainloop ring)
        struct {
            float att[64][132];
            float l[64][8];
            float w[16][132];
        } e;                                         // 44.3 KB (epilogue)
    } sm;

    int cta = blockIdx.x;
    int b = cta / 36, g = cta % 36;
    int gy = g / 6, gx = g % 6;
    int tid  = threadIdx.x;
    int lane = tid & 31;
    int warp = tid >> 5;
    int h = warp & 7, th = warp >> 3;     // head, row-half

    int qg0 = lane, qg1 = lane + 32;
    int wgA = qg0 >> 4, wgB = qg1 >> 4;   // wgA in {0,1}, wgB in {2,3}

    const float SC = 0.25f * 1.4426950408889634f;
    u64 SC2 = pk2(SC, SC);

    // ---- load 2 queries (16 dims each), pre-scaled ----
    u64 q0[8], q1[8];
    {
        int qi = qg0 & 15;
        int wy = gy*2 + (wgA>>1), wx = gx*2 + (wgA&1);
        int py = wy*4 + (qi>>2), px = wx*4 + (qi&3);
        const longlong2* qp = (const longlong2*)(g_Q + ((size_t)((b*48+py)*48+px))*128 + h*16);
#pragma unroll
        for (int i = 0; i < 4; i++) {
            longlong2 t2 = qp[i];
            q0[2*i]   = fmul2((u64)t2.x, SC2);
            q0[2*i+1] = fmul2((u64)t2.y, SC2);
        }
    }
    {
        int qi = qg1 & 15;
        int wy = gy*2 + (wgB>>1), wx = gx*2 + (wgB&1);
        int py = wy*4 + (qi>>2), px = wx*4 + (qi&3);
        const longlong2* qp = (const longlong2*)(g_Q + ((size_t)((b*48+py)*48+px))*128 + h*16);
#pragma unroll
        for (int i = 0; i < 4; i++) {
            longlong2 t2 = qp[i];
            q1[2*i]   = fmul2((u64)t2.x, SC2);
            q1[2*i+1] = fmul2((u64)t2.y, SC2);
        }
    }

    u64 acc0[8], acc1[8];
#pragma unroll
    for (int i = 0; i < 8; i++) { acc0[i] = 0ull; acc1[i] = 0ull; }
    float ls0 = 0.f, ls1 = 0.f;

    // staging map (R5): 16 rows, 32 threads/row, 8 floats (2x cp16) each
    int srow = tid >> 5;
    int scol = (tid & 31) * 8;

    auto stage = [&](int tt, int buf) {
        const float* src;
        if (tt < 16) {
            int wgl = tt >> 2, st = tt & 3;
            int idx = st*16 + srow;
            int y = (gy*2 + (wgl>>1))*4 + (idx>>3) - 2;
            int x = (gx*2 + (wgl&1))*4  + (idx&7)  - 2;
            src = ((unsigned)y < 48u && (unsigned)x < 48u)
                ? (g_KV + ((size_t)((b*48+y)*48+x))*256) : kvb;
        } else if (tt < 52) {
            src = g_KVmid + ((size_t)(b*576 + (tt-16)*16 + srow))*256;
        } else {
            src = g_KVglo + ((size_t)(b*144 + (tt-52)*16 + srow))*256;
        }
        uint32_t dst = (uint32_t)__cvta_generic_to_shared(&sm.kv[buf][srow][scol]);
        cp16(dst,      src + scol);
        cp16(dst + 16, src + scol + 4);
        asm volatile("cp.async.commit_group;");
    };

    stage(0, 0);

    for (int t = 0; t < NTILE; t++) {
        if (t + 1 < NTILE) {
            stage(t+1, (t+1)&1);
            asm volatile("cp.async.wait_group 1;");
        } else {
            asm volatile("cp.async.wait_group 0;");
        }
        __syncthreads();

        // this warp-half computes rows [th*8, th*8+8) of the tile
        const float* kbase = &sm.kv[t&1][th*8][h*16];

        if (t < 16) {
            // ---- local tile: only the matching query path ----
            int wgl = t >> 2;
            if (wgl < 2) {
                u64 mb = pk2((wgA == wgl) ? 0.f : -1e30f, 0.f);
#pragma unroll
                for (int j = 0; j < 8; j++) {
                    const longlong2* kp = (const longlong2*)(kbase + j*256);
                    longlong2 a0 = kp[0], a1 = kp[1], a2 = kp[2], a3 = kp[3];
                    u64 d0 = ffma2(q0[0], (u64)a0.x, mb);
                    d0 = ffma2(q0[1], (u64)a0.y, d0);
                    d0 = ffma2(q0[2], (u64)a1.x, d0);
                    d0 = ffma2(q0[3], (u64)a1.y, d0);
                    d0 = ffma2(q0[4], (u64)a2.x, d0);
                    d0 = ffma2(q0[5], (u64)a2.y, d0);
                    d0 = ffma2(q0[6], (u64)a3.x, d0);
                    d0 = ffma2(q0[7], (u64)a3.y, d0);
                    float a, bb;
                    up2(d0, a, bb); float p0 = ex2f(a + bb);
                    ls0 += p0;
                    u64 P0 = pk2(p0, p0);
                    const longlong2* vp = (const longlong2*)(kbase + j*256 + 128);
                    longlong2 v0 = vp[0], v1 = vp[1], v2 = vp[2], v3 = vp[3];
                    acc0[0] = ffma2(P0, (u64)v0.x, acc0[0]);
                    acc0[1] = ffma2(P0, (u64)v0.y, acc0[1]);
                    acc0[2] = ffma2(P0, (u64)v1.x, acc0[2]);
                    acc0[3] = ffma2(P0, (u64)v1.y, acc0[3]);
                    acc0[4] = ffma2(P0, (u64)v2.x, acc0[4]);
                    acc0[5] = ffma2(P0, (u64)v2.y, acc0[5]);
                    acc0[6] = ffma2(P0, (u64)v3.x, acc0[6]);
                    acc0[7] = ffma2(P0, (u64)v3.y, acc0[7]);
                }
            } else {
                u64 mb = pk2((wgB == wgl) ? 0.f : -1e30f, 0.f);
#pragma unroll
                for (int j = 0; j < 8; j++) {
                    const longlong2* kp = (const longlong2*)(kbase + j*256);
                    longlong2 a0 = kp[0], a1 = kp[1], a2 = kp[2], a3 = kp[3];
                    u64 d1 = ffma2(q1[0], (u64)a0.x, mb);
                    d1 = ffma2(q1[1], (u64)a0.y, d1);
                    d1 = ffma2(q1[2], (u64)a1.x, d1);
                    d1 = ffma2(q1[3], (u64)a1.y, d1);
                    d1 = ffma2(q1[4], (u64)a2.x, d1);
                    d1 = ffma2(q1[5], (u64)a2.y, d1);
                    d1 = ffma2(q1[6], (u64)a3.x, d1);
                    d1 = ffma2(q1[7], (u64)a3.y, d1);
                    float a, bb;
                    up2(d1, a, bb); float p1 = ex2f(a + bb);
                    ls1 += p1;
                    u64 P1 = pk2(p1, p1);
                    const longlong2* vp = (const longlong2*)(kbase + j*256 + 128);
                    longlong2 v0 = vp[0], v1 = vp[1], v2 = vp[2], v3 = vp[3];
                    acc1[0] = ffma2(P1, (u64)v0.x, acc1[0]);
                    acc1[1] = ffma2(P1, (u64)v0.y, acc1[1]);
                    acc1[2] = ffma2(P1, (u64)v1.x, acc1[2]);
                    acc1[3] = ffma2(P1, (u64)v1.y, acc1[3]);
                    acc1[4] = ffma2(P1, (u64)v2.x, acc1[4]);
                    acc1[5] = ffma2(P1, (u64)v2.y, acc1[5]);
                    acc1[6] = ffma2(P1, (u64)v3.x, acc1[6]);
                    acc1[7] = ffma2(P1, (u64)v3.y, acc1[7]);
                }
            }
        } else {
            // ---- mid/glo tile: both query paths, no masks ----
#pragma unroll 4
            for (int j = 0; j < 8; j++) {
                const longlong2* kp = (const longlong2*)(kbase + j*256);
                longlong2 a0 = kp[0], a1 = kp[1], a2 = kp[2], a3 = kp[3];

                u64 d0 = fmul2(q0[0], (u64)a0.x);
                d0 = ffma2(q0[1], (u64)a0.y, d0);
                d0 = ffma2(q0[2], (u64)a1.x, d0);
                d0 = ffma2(q0[3], (u64)a1.y, d0);
                d0 = ffma2(q0[4], (u64)a2.x, d0);
                d0 = ffma2(q0[5], (u64)a2.y, d0);
                d0 = ffma2(q0[6], (u64)a3.x, d0);
                d0 = ffma2(q0[7], (u64)a3.y, d0);
                u64 d1 = fmul2(q1[0], (u64)a0.x);
                d1 = ffma2(q1[1], (u64)a0.y, d1);
                d1 = ffma2(q1[2], (u64)a1.x, d1);
                d1 = ffma2(q1[3], (u64)a1.y, d1);
                d1 = ffma2(q1[4], (u64)a2.x, d1);
                d1 = ffma2(q1[5], (u64)a2.y, d1);
                d1 = ffma2(q1[6], (u64)a3.x, d1);
                d1 = ffma2(q1[7], (u64)a3.y, d1);

                float a, bb;
                up2(d0, a, bb); float p0 = ex2f(a + bb);
                up2(d1, a, bb); float p1 = ex2f(a + bb);
                ls0 += p0; ls1 += p1;
                u64 P0 = pk2(p0, p0), P1 = pk2(p1, p1);

                const longlong2* vp = (const longlong2*)(kbase + j*256 + 128);
                longlong2 v0 = vp[0], v1 = vp[1], v2 = vp[2], v3 = vp[3];
                acc0[0] = ffma2(P0, (u64)v0.x, acc0[0]);
                acc0[1] = ffma2(P0, (u64)v0.y, acc0[1]);
                acc0[2] = ffma2(P0, (u64)v1.x, acc0[2]);
                acc0[3] = ffma2(P0, (u64)v1.y, acc0[3]);
                acc0[4] = ffma2(P0, (u64)v2.x, acc0[4]);
                acc0[5] = ffma2(P0, (u64)v2.y, acc0[5]);
                acc0[6] = ffma2(P0, (u64)v3.x, acc0[6]);
                acc0[7] = ffma2(P0, (u64)v3.y, acc0[7]);
                acc1[0] = ffma2(P1, (u64)v0.x, acc1[0]);
                acc1[1] = ffma2(P1, (u64)v0.y, acc1[1]);
                acc1[2] = ffma2(P1, (u64)v1.x, acc1[2]);
                acc1[3] = ffma2(P1, (u64)v1.y, acc1[3]);
                acc1[4] = ffma2(P1, (u64)v2.x, acc1[4]);
                acc1[5] = ffma2(P1, (u64)v2.y, acc1[5]);
                acc1[6] = ffma2(P1, (u64)v3.x, acc1[6]);
                acc1[7] = ffma2(P1, (u64)v3.y, acc1[7]);
            }
        }
        __syncthreads();
    }

    // ---- merge the two row-halves via smem, normalize ----
    if (th == 0) {
        float* r0 = &sm.e.att[qg0][h*16];
        float* r1 = &sm.e.att[qg1][h*16];
#pragma unroll
        for (int i = 0; i < 8; i++) {
            float a, bb;
            up2(acc0[i], a, bb); r0[2*i] = a; r0[2*i+1] = bb;
            up2(acc1[i], a, bb); r1[2*i] = a; r1[2*i+1] = bb;
        }
        sm.e.l[qg0][h] = ls0;
        sm.e.l[qg1][h] = ls1;
    }
    __syncthreads();
    if (th == 1) {
        float inv0 = 1.f / (sm.e.l[qg0][h] + ls0);
        float inv1 = 1.f / (sm.e.l[qg1][h] + ls1);
        float* r0 = &sm.e.att[qg0][h*16];
        float* r1 = &sm.e.att[qg1][h*16];
#pragma unroll
        for (int i = 0; i < 8; i++) {
            float a, bb;
            up2(acc0[i], a, bb);
            r0[2*i]   = (r0[2*i]   + a ) * inv0;
            r0[2*i+1] = (r0[2*i+1] + bb) * inv0;
            up2(acc1[i], a, bb);
            r1[2*i]   = (r1[2*i]   + a ) * inv1;
            r1[2*i+1] = (r1[2*i+1] + bb) * inv1;
        }
    }
    __syncthreads();

    // ---- out projection: thread = (aqi = tid>>3, og = tid&7) ----
    int aqi = tid >> 3, og = tid & 7;
    float o[16];
#pragma unroll 1
    for (int ch = 0; ch < 8; ch++) {
        {
            int row = tid >> 5, quad = tid & 31;
            *(float4*)&sm.e.w[row][quad*4] =
                *(const float4*)(ow + (size_t)(ch*16 + row)*128 + quad*4);
        }
        __syncthreads();
        u64 r0p = 0ull, r1p = 0ull;
#pragma unroll
        for (int k4 = 0; k4 < 32; k4++) {
            longlong2 av = *(const longlong2*)&sm.e.att[aqi][k4*4];
            longlong2 w0 = *(const longlong2*)&sm.e.w[og][k4*4];
            longlong2 w1 = *(const longlong2*)&sm.e.w[og+8][k4*4];
            r0p = ffma2((u64)av.x, (u64)w0.x, r0p);
            r0p = ffma2((u64)av.y, (u64)w0.y, r0p);
            r1p = ffma2((u64)av.x, (u64)w1.x, r1p);
            r1p = ffma2((u64)av.y, (u64)w1.y, r1p);
        }
        float a, bb;
        up2(r0p, a, bb); o[ch*2]   = a + bb;
        up2(r1p, a, bb); o[ch*2+1] = a + bb;
        __syncthreads();
    }

    // ---- residual add + NCHW scatter store ----
    {
        int qi = aqi & 15, wq = aqi >> 4;
        int wy = gy*2 + (wq>>1), wx = gx*2 + (wq&1);
        int py = wy*4 + (qi>>2), px = wx*4 + (qi&3);
#pragma unroll
        for (int ch = 0; ch < 8; ch++) {
#pragma unroll
            for (int u2 = 0; u2 < 2; u2++) {
                int oc = ch*16 + u2*8 + og;
                size_t gi = (((size_t)b*128 + oc)*48 + py)*48 + px;
                out[gi] = o[ch*2+u2] + ob[oc] + feat[gi];
            }
        }
    }
}

// ============================================================================
extern "C" void kernel_launch(void* const* d_in, const int* in_sizes, int n_in,
                              void* d_out, int out_size) {
    const float* feat = (const float*)d_in[0];
    const float* lnw  = (const float*)d_in[1];
    const float* lnb  = (const float*)d_in[2];
    const float* qw   = (const float*)d_in[3];
    const float* qb   = (const float*)d_in[4];
    const float* kvw  = (const float*)d_in[5];
    const float* kvb  = (const float*)d_in[6];
    const float* ow   = (const float*)d_in[7];
    const float* ob   = (const float*)d_in[8];
    float* out = (float*)d_out;

    k0_ln<<<1152, 256>>>(feat, lnw, lnb);
    k1_gemm<<<dim3(144, 3), 256>>>(qw, qb, kvw, kvb);
    k2_pool<<<2880, 256>>>();
    k3_attn<<<144, 512>>>(feat, kvb, ow, ob, out);
}

// round 9
// speedup vs baseline: 1.3032x; 1.0090x over previous
#include <cuda_runtime.h>
#include <cstdint>

// Problem constants
#define BB 4
#define HH 48
#define WW 48
#define CC 128

typedef unsigned long long u64;

// ---------------- scratch (device globals; no allocation allowed) ----------
__device__ float g_F [BB*HH*WW*CC];      // raw features, pixel-major
__device__ float g_FN[BB*HH*WW*CC];      // layernormed features, pixel-major
__device__ float g_Q [BB*HH*WW*CC];      // queries per pixel
__device__ float g_KV[BB*HH*WW*256];     // per-pixel KV projection (K|V)
__device__ float g_KVmid[BB*24*24*256];  // 2x2 pooled KV
__device__ float g_KVglo[BB*12*12*256];  // 4x4 pooled KV

__device__ __forceinline__ float ex2f(float x) {
    float r; asm("ex2.approx.f32 %0, %1;" : "=f"(r) : "f"(x)); return r;
}
__device__ __forceinline__ u64 ffma2(u64 a, u64 b, u64 c) {
    u64 d; asm("fma.rn.f32x2 %0,%1,%2,%3;" : "=l"(d) : "l"(a), "l"(b), "l"(c)); return d;
}
__device__ __forceinline__ u64 fmul2(u64 a, u64 b) {
    u64 d; asm("mul.rn.f32x2 %0,%1,%2;" : "=l"(d) : "l"(a), "l"(b)); return d;
}
__device__ __forceinline__ u64 pk2(float lo, float hi) {
    u64 d; asm("mov.b64 %0,{%1,%2};" : "=l"(d) : "f"(lo), "f"(hi)); return d;
}
__device__ __forceinline__ void up2(u64 v, float& lo, float& hi) {
    asm("mov.b64 {%0,%1},%2;" : "=f"(lo), "=f"(hi) : "l"(v));
}
__device__ __forceinline__ void cp16(uint32_t dst, const float* src) {
    asm volatile("cp.async.cg.shared.global [%0], [%1], 16;" :: "r"(dst), "l"(src));
}

// ============================================================================
// Kernel 0: transpose NCHW -> pixel-major + LayerNorm.  One warp per pixel.
// ============================================================================
__global__ void k0_ln(const float* __restrict__ feat,
                      const float* __restrict__ lnw,
                      const float* __restrict__ lnb) {
    int warp = (blockIdx.x * blockDim.x + threadIdx.x) >> 5;
    int lane = threadIdx.x & 31;
    if (warp >= BB*HH*WW) return;
    int b   = warp / (HH*WW);
    int rem = warp % (HH*WW);
    const float* src = feat + (size_t)b * CC * HH * WW + rem;

    float v[4];
    float s = 0.f, ss = 0.f;
#pragma unroll
    for (int i = 0; i < 4; i++) {
        int c = lane + 32*i;
        v[i] = src[(size_t)c * (HH*WW)];
        s  += v[i];
        ss += v[i]*v[i];
    }
#pragma unroll
    for (int o = 16; o; o >>= 1) {
        s  += __shfl_xor_sync(0xffffffffu, s,  o);
        ss += __shfl_xor_sync(0xffffffffu, ss, o);
    }
    float mean = s * (1.f/128.f);
    float var  = ss * (1.f/128.f) - mean*mean;
    float rstd = rsqrtf(var + 1e-5f);

    float* dF = g_F  + (size_t)warp * CC;
    float* dN = g_FN + (size_t)warp * CC;
#pragma unroll
    for (int i = 0; i < 4; i++) {
        int c = lane + 32*i;
        dF[c] = v[i];
        dN[c] = (v[i] - mean) * rstd * lnw[c] + lnb[c];
    }
}

// ============================================================================
// Kernel 1: fused GEMMs (Q / K / V projections).  Unchanged (known good).
// ============================================================================
#define MT 64
#define PADK 36

__global__ void k1_gemm(const float* __restrict__ qw, const float* __restrict__ qb,
                        const float* __restrict__ kvw, const float* __restrict__ kvb) {
    __shared__ float sA[MT][PADK];
    __shared__ float sB[128][PADK];

    int sub   = blockIdx.y;
    int mBase = blockIdx.x * MT;
    const float* A    = (sub == 0) ? g_FN : g_F;
    const float* Wm   = (sub == 0) ? qw : (kvw + (size_t)(sub-1)*128*128);
    const float* bias = (sub == 0) ? qb : (kvb + (sub-1)*128);

    int tid = threadIdx.x;
    int mg = tid & 15;
    int ng = tid >> 4;

    float acc[4][8];
#pragma unroll
    for (int m = 0; m < 4; m++)
#pragma unroll
        for (int n = 0; n < 8; n++) acc[m][n] = 0.f;

    for (int ck = 0; ck < 4; ck++) {
        __syncthreads();
#pragma unroll
        for (int i = 0; i < 2; i++) {
            int f = tid + i*256;
            int pix = f >> 3, kq = f & 7;
            float4 val = *(const float4*)(A + (size_t)(mBase+pix)*128 + ck*32 + kq*4);
            *(float4*)&sA[pix][kq*4] = val;
        }
#pragma unroll
        for (int i = 0; i < 4; i++) {
            int f = tid + i*256;
            int row = f >> 3, kq = f & 7;
            float4 val = *(const float4*)(Wm + (size_t)row*128 + ck*32 + kq*4);
            *(float4*)&sB[row][kq*4] = val;
        }
        __syncthreads();

#pragma unroll
        for (int k4 = 0; k4 < 8; k4++) {
            float4 a0 = *(const float4*)&sA[mg*4+0][k4*4];
            float4 a1 = *(const float4*)&sA[mg*4+1][k4*4];
            float4 a2 = *(const float4*)&sA[mg*4+2][k4*4];
            float4 a3 = *(const float4*)&sA[mg*4+3][k4*4];
#pragma unroll
            for (int n = 0; n < 8; n++) {
                float4 bv = *(const float4*)&sB[ng*8+n][k4*4];
                acc[0][n] += a0.x*bv.x + a0.y*bv.y + a0.z*bv.z + a0.w*bv.w;
                acc[1][n] += a1.x*bv.x + a1.y*bv.y + a1.z*bv.z + a1.w*bv.w;
                acc[2][n] += a2.x*bv.x + a2.y*bv.y + a2.z*bv.z + a2.w*bv.w;
                acc[3][n] += a3.x*bv.x + a3.y*bv.y + a3.z*bv.z + a3.w*bv.w;
            }
        }
    }

    float4 bv0 = *(const float4*)(bias + ng*8);
    float4 bv1 = *(const float4*)(bias + ng*8 + 4);
    int stride = (sub == 0) ? 128 : 256;
    float* base = (sub == 0) ? (g_Q + ng*8) : (g_KV + (sub-1)*128 + ng*8);
#pragma unroll
    for (int m = 0; m < 4; m++) {
        float* dst = base + (size_t)(mBase + mg*4 + m) * stride;
        float4 r0 = make_float4(acc[m][0]+bv0.x, acc[m][1]+bv0.y, acc[m][2]+bv0.z, acc[m][3]+bv0.w);
        float4 r1 = make_float4(acc[m][4]+bv1.x, acc[m][5]+bv1.y, acc[m][6]+bv1.z, acc[m][7]+bv1.w);
        *(float4*)dst       = r0;
        *((float4*)dst + 1) = r1;
    }
}

// ============================================================================
// Kernel 2: pooled KV.  Unchanged.
// ============================================================================
__global__ void k2_pool() {
    int t = blockIdx.x;
    int c = threadIdx.x;
    if (t < BB*576) {
        int b = t / 576, r = t % 576, my = r / 24, mx = r % 24;
        const float* base = g_KV + ((size_t)((b*48 + my*2)*48 + mx*2))*256 + c;
        float v = base[0] + base[256] + base[48*256] + base[48*256 + 256];
        g_KVmid[(size_t)t*256 + c] = v * 0.25f;
    } else {
        int t2 = t - BB*576;
        int b = t2 / 144, r = t2 % 144, gy = r / 12, gx = r % 12;
        float v = 0.f;
#pragma unroll
        for (int i = 0; i < 4; i++)
#pragma unroll
            for (int j = 0; j < 4; j++)
                v += g_KV[((size_t)((b*48 + gy*4 + i)*48 + gx*4 + j))*256 + c];
        g_KVglo[(size_t)t2*256 + c] = v * (1.f/16.f);
    }
}

// ============================================================================
// Kernel 3 v8 (= R8 + decoupled halves + 2 tiles/step):
//   - 2 tiles (32 rows) per ring slot; ring = 2 x 32KB dynamic smem.
//   - Each warp-half (th = warp>>3) STAGES exactly the tile rows it CONSUMES
//     (rows th*8..th*8+7 of each 16-row tile) -> halves are fully independent
//     in the mainloop; per-tile __syncthreads replaced by per-half
//     bar.sync (id 1+th, 256 threads).  Barrier count 122 -> 62, scope halved.
//   - Compute per tile identical to R8 (local: matching query path only;
//     mid/glo: both paths).  Full __syncthreads only before epilogue merge.
// ============================================================================
#define NSTEP 31     // 31 steps x 2 tiles = 62 (tile 61 = pad)

__global__ void __launch_bounds__(512, 1)
k3_attn(const float* __restrict__ feat, const float* __restrict__ kvb,
        const float* __restrict__ ow,   const float* __restrict__ ob,
        float* __restrict__ out) {
    extern __shared__ float ds[];    // 65536 B: ring[2][32][256]

    int cta = blockIdx.x;
    int b = cta / 36, g = cta % 36;
    int gy = g / 6, gx = g % 6;
    int tid  = threadIdx.x;
    int lane = tid & 31;
    int warp = tid >> 5;
    int h = warp & 7, th = warp >> 3;     // head, half
    int barid = 1 + th;

    int qg0 = lane, qg1 = lane + 32;
    int wgA = qg0 >> 4, wgB = qg1 >> 4;   // wgA in {0,1}, wgB in {2,3}

    const float SC = 0.25f * 1.4426950408889634f;
    u64 SC2 = pk2(SC, SC);

    // ---- load 2 queries (16 dims each), pre-scaled ----
    u64 q0[8], q1[8];
    {
        int qi = qg0 & 15;
        int wy = gy*2 + (wgA>>1), wx = gx*2 + (wgA&1);
        int py = wy*4 + (qi>>2), px = wx*4 + (qi&3);
        const longlong2* qp = (const longlong2*)(g_Q + ((size_t)((b*48+py)*48+px))*128 + h*16);
#pragma unroll
        for (int i = 0; i < 4; i++) {
            longlong2 t2 = qp[i];
            q0[2*i]   = fmul2((u64)t2.x, SC2);
            q0[2*i+1] = fmul2((u64)t2.y, SC2);
        }
    }
    {
        int qi = qg1 & 15;
        int wy = gy*2 + (wgB>>1), wx = gx*2 + (wgB&1);
        int py = wy*4 + (qi>>2), px = wx*4 + (qi&3);
        const longlong2* qp = (const longlong2*)(g_Q + ((size_t)((b*48+py)*48+px))*128 + h*16);
#pragma unroll
        for (int i = 0; i < 4; i++) {
            longlong2 t2 = qp[i];
            q1[2*i]   = fmul2((u64)t2.x, SC2);
            q1[2*i+1] = fmul2((u64)t2.y, SC2);
        }
    }

    u64 acc0[8], acc1[8];
#pragma unroll
    for (int i = 0; i < 8; i++) { acc0[i] = 0ull; acc1[i] = 0ull; }
    float ls0 = 0.f, ls1 = 0.f;

    // staging: each half's 256 threads stage its 8 consumed rows per tile.
    // idx in [0,256): sub = idx>>4 selects one of 16 (tile,row) pairs,
    // (idx&15)*16 = 16-float column segment (4x cp16).
    int idx   = tid & 255;
    int sub   = idx >> 4;
    int rowit = th*8 + (sub & 7);     // row-in-tile this half consumes
    int tsel  = sub >> 3;             // which tile of the pair
    int scol  = (idx & 15) * 16;

    auto stage = [&](int s, int buf) {
        int tt = 2*s + tsel;
        const float* src;
        if (tt < 16) {
            int wgl = tt >> 2, st = tt & 3;
            int id2 = st*16 + rowit;
            int y = (gy*2 + (wgl>>1))*4 + (id2>>3) - 2;
            int x = (gx*2 + (wgl&1))*4  + (id2&7)  - 2;
            src = ((unsigned)y < 48u && (unsigned)x < 48u)
                ? (g_KV + ((size_t)((b*48+y)*48+x))*256) : kvb;
        } else if (tt < 52) {
            src = g_KVmid + ((size_t)(b*576 + (tt-16)*16 + rowit))*256;
        } else if (tt < 61) {
            src = g_KVglo + ((size_t)(b*144 + (tt-52)*16 + rowit))*256;
        } else {
            src = kvb;                // pad tile (never computed)
        }
        uint32_t dst = (uint32_t)__cvta_generic_to_shared(
            ds + buf*8192 + (tsel*16 + rowit)*256 + scol);
        cp16(dst,      src + scol);
        cp16(dst + 16, src + scol + 4);
        cp16(dst + 32, src + scol + 8);
        cp16(dst + 48, src + scol + 12);
        asm volatile("cp.async.commit_group;");
    };

    // per-tile compute (rows th*8..th*8+7)
    auto compute = [&](const float* kbase, int tt) {
        if (tt < 16) {
            int wgl = tt >> 2;
            if (wgl < 2) {
                u64 mb = pk2((wgA == wgl) ? 0.f : -1e30f, 0.f);
#pragma unroll
                for (int j = 0; j < 8; j++) {
                    const longlong2* kp = (const longlong2*)(kbase + j*256);
                    longlong2 a0 = kp[0], a1 = kp[1], a2 = kp[2], a3 = kp[3];
                    u64 d0 = ffma2(q0[0], (u64)a0.x, mb);
                    d0 = ffma2(q0[1], (u64)a0.y, d0);
                    d0 = ffma2(q0[2], (u64)a1.x, d0);
                    d0 = ffma2(q0[3], (u64)a1.y, d0);
                    d0 = ffma2(q0[4], (u64)a2.x, d0);
                    d0 = ffma2(q0[5], (u64)a2.y, d0);
                    d0 = ffma2(q0[6], (u64)a3.x, d0);
                    d0 = ffma2(q0[7], (u64)a3.y, d0);
                    float a, bb;
                    up2(d0, a, bb); float p0 = ex2f(a + bb);
                    ls0 += p0;
                    u64 P0 = pk2(p0, p0);
                    const longlong2* vp = (const longlong2*)(kbase + j*256 + 128);
                    longlong2 v0 = vp[0], v1 = vp[1], v2 = vp[2], v3 = vp[3];
                    acc0[0] = ffma2(P0, (u64)v0.x, acc0[0]);
                    acc0[1] = ffma2(P0, (u64)v0.y, acc0[1]);
                    acc0[2] = ffma2(P0, (u64)v1.x, acc0[2]);
                    acc0[3] = ffma2(P0, (u64)v1.y, acc0[3]);
                    acc0[4] = ffma2(P0, (u64)v2.x, acc0[4]);
                    acc0[5] = ffma2(P0, (u64)v2.y, acc0[5]);
                    acc0[6] = ffma2(P0, (u64)v3.x, acc0[6]);
                    acc0[7] = ffma2(P0, (u64)v3.y, acc0[7]);
                }
            } else {
                u64 mb = pk2((wgB == wgl) ? 0.f : -1e30f, 0.f);
#pragma unroll
                for (int j = 0; j < 8; j++) {
                    const longlong2* kp = (const longlong2*)(kbase + j*256);
                    longlong2 a0 = kp[0], a1 = kp[1], a2 = kp[2], a3 = kp[3];
                    u64 d1 = ffma2(q1[0], (u64)a0.x, mb);
                    d1 = ffma2(q1[1], (u64)a0.y, d1);
                    d1 = ffma2(q1[2], (u64)a1.x, d1);
                    d1 = ffma2(q1[3], (u64)a1.y, d1);
                    d1 = ffma2(q1[4], (u64)a2.x, d1);
                    d1 = ffma2(q1[5], (u64)a2.y, d1);
                    d1 = ffma2(q1[6], (u64)a3.x, d1);
                    d1 = ffma2(q1[7], (u64)a3.y, d1);
                    float a, bb;
                    up2(d1, a, bb); float p1 = ex2f(a + bb);
                    ls1 += p1;
                    u64 P1 = pk2(p1, p1);
                    const longlong2* vp = (const longlong2*)(kbase + j*256 + 128);
                    longlong2 v0 = vp[0], v1 = vp[1], v2 = vp[2], v3 = vp[3];
                    acc1[0] = ffma2(P1, (u64)v0.x, acc1[0]);
                    acc1[1] = ffma2(P1, (u64)v0.y, acc1[1]);
                    acc1[2] = ffma2(P1, (u64)v1.x, acc1[2]);
                    acc1[3] = ffma2(P1, (u64)v1.y, acc1[3]);
                    acc1[4] = ffma2(P1, (u64)v2.x, acc1[4]);
                    acc1[5] = ffma2(P1, (u64)v2.y, acc1[5]);
                    acc1[6] = ffma2(P1, (u64)v3.x, acc1[6]);
                    acc1[7] = ffma2(P1, (u64)v3.y, acc1[7]);
                }
            }
        } else {
#pragma unroll 4
            for (int j = 0; j < 8; j++) {
                const longlong2* kp = (const longlong2*)(kbase + j*256);
                longlong2 a0 = kp[0], a1 = kp[1], a2 = kp[2], a3 = kp[3];

                u64 d0 = fmul2(q0[0], (u64)a0.x);
                d0 = ffma2(q0[1], (u64)a0.y, d0);
                d0 = ffma2(q0[2], (u64)a1.x, d0);
                d0 = ffma2(q0[3], (u64)a1.y, d0);
                d0 = ffma2(q0[4], (u64)a2.x, d0);
                d0 = ffma2(q0[5], (u64)a2.y, d0);
                d0 = ffma2(q0[6], (u64)a3.x, d0);
                d0 = ffma2(q0[7], (u64)a3.y, d0);
                u64 d1 = fmul2(q1[0], (u64)a0.x);
                d1 = ffma2(q1[1], (u64)a0.y, d1);
                d1 = ffma2(q1[2], (u64)a1.x, d1);
                d1 = ffma2(q1[3], (u64)a1.y, d1);
                d1 = ffma2(q1[4], (u64)a2.x, d1);
                d1 = ffma2(q1[5], (u64)a2.y, d1);
                d1 = ffma2(q1[6], (u64)a3.x, d1);
                d1 = ffma2(q1[7], (u64)a3.y, d1);

                float a, bb;
                up2(d0, a, bb); float p0 = ex2f(a + bb);
                up2(d1, a, bb); float p1 = ex2f(a + bb);
                ls0 += p0; ls1 += p1;
                u64 P0 = pk2(p0, p0), P1 = pk2(p1, p1);

                const longlong2* vp = (const longlong2*)(kbase + j*256 + 128);
                longlong2 v0 = vp[0], v1 = vp[1], v2 = vp[2], v3 = vp[3];
                acc0[0] = ffma2(P0, (u64)v0.x, acc0[0]);
                acc0[1] = ffma2(P0, (u64)v0.y, acc0[1]);
                acc0[2] = ffma2(P0, (u64)v1.x, acc0[2]);
                acc0[3] = ffma2(P0, (u64)v1.y, acc0[3]);
                acc0[4] = ffma2(P0, (u64)v2.x, acc0[4]);
                acc0[5] = ffma2(P0, (u64)v2.y, acc0[5]);
                acc0[6] = ffma2(P0, (u64)v3.x, acc0[6]);
                acc0[7] = ffma2(P0, (u64)v3.y, acc0[7]);
                acc1[0] = ffma2(P1, (u64)v0.x, acc1[0]);
                acc1[1] = ffma2(P1, (u64)v0.y, acc1[1]);
                acc1[2] = ffma2(P1, (u64)v1.x, acc1[2]);
                acc1[3] = ffma2(P1, (u64)v1.y, acc1[3]);
                acc1[4] = ffma2(P1, (u64)v2.x, acc1[4]);
                acc1[5] = ffma2(P1, (u64)v2.y, acc1[5]);
                acc1[6] = ffma2(P1, (u64)v3.x, acc1[6]);
                acc1[7] = ffma2(P1, (u64)v3.y, acc1[7]);
            }
        }
    };

    stage(0, 0);

    for (int s = 0; s < NSTEP; s++) {
        if (s + 1 < NSTEP) {
            stage(s+1, (s+1)&1);
            asm volatile("cp.async.wait_group 1;");
        } else {
            asm volatile("cp.async.wait_group 0;");
        }
        asm volatile("bar.sync %0, %1;" :: "r"(barid), "r"(256) : "memory");

        const float* buf = ds + (s&1)*8192;
        int t0 = 2*s;
        compute(buf + (th*8)*256 + h*16, t0);
        if (t0 + 1 < 61)
            compute(buf + (16 + th*8)*256 + h*16, t0 + 1);

        asm volatile("bar.sync %0, %1;" :: "r"(barid), "r"(256) : "memory");
    }

    // ---- full barrier: both halves done with the ring before reuse ----
    __syncthreads();

    // ------------------- merge halves, normalize, epilogue -----------------
    float* att = ds;                    // [64][132]
    float* lsm = ds + 64*132;           // [64][8]
    float* wsm = ds + 64*132 + 64*8;    // [16][132]

    if (th == 0) {
        float* r0 = &att[qg0*132 + h*16];
        float* r1 = &att[qg1*132 + h*16];
#pragma unroll
        for (int i = 0; i < 8; i++) {
            float a, bb;
            up2(acc0[i], a, bb); r0[2*i] = a; r0[2*i+1] = bb;
            up2(acc1[i], a, bb); r1[2*i] = a; r1[2*i+1] = bb;
        }
        lsm[qg0*8 + h] = ls0;
        lsm[qg1*8 + h] = ls1;
    }
    __syncthreads();
    if (th == 1) {
        float inv0 = 1.f / (lsm[qg0*8 + h] + ls0);
        float inv1 = 1.f / (lsm[qg1*8 + h] + ls1);
        float* r0 = &att[qg0*132 + h*16];
        float* r1 = &att[qg1*132 + h*16];
#pragma unroll
        for (int i = 0; i < 8; i++) {
            float a, bb;
            up2(acc0[i], a, bb);
            r0[2*i]   = (r0[2*i]   + a ) * inv0;
            r0[2*i+1] = (r0[2*i+1] + bb) * inv0;
            up2(acc1[i], a, bb);
            r1[2*i]   = (r1[2*i]   + a ) * inv1;
            r1[2*i+1] = (r1[2*i+1] + bb) * inv1;
        }
    }
    __syncthreads();

    // ---- out projection: thread = (aqi = tid>>3, og = tid&7) ----
    int aqi = tid >> 3, og = tid & 7;
    float o[16];
#pragma unroll 1
    for (int ch = 0; ch < 8; ch++) {
        {
            int row = tid >> 5, quad = tid & 31;
            *(float4*)&wsm[row*132 + quad*4] =
                *(const float4*)(ow + (size_t)(ch*16 + row)*128 + quad*4);
        }
        __syncthreads();
        u64 r0p = 0ull, r1p = 0ull;
#pragma unroll
        for (int k4 = 0; k4 < 32; k4++) {
            longlong2 av = *(const longlong2*)&att[aqi*132 + k4*4];
            longlong2 w0 = *(const longlong2*)&wsm[og*132 + k4*4];
            longlong2 w1 = *(const longlong2*)&wsm[(og+8)*132 + k4*4];
            r0p = ffma2((u64)av.x, (u64)w0.x, r0p);
            r0p = ffma2((u64)av.y, (u64)w0.y, r0p);
            r1p = ffma2((u64)av.x, (u64)w1.x, r1p);
            r1p = ffma2((u64)av.y, (u64)w1.y, r1p);
        }
        float a, bb;
        up2(r0p, a, bb); o[ch*2]   = a + bb;
        up2(r1p, a, bb); o[ch*2+1] = a + bb;
        __syncthreads();
    }

    // ---- residual add + NCHW scatter store ----
    {
        int qi = aqi & 15, wq = aqi >> 4;
        int wy = gy*2 + (wq>>1), wx = gx*2 + (wq&1);
        int py = wy*4 + (qi>>2), px = wx*4 + (qi&3);
#pragma unroll
        for (int ch = 0; ch < 8; ch++) {
#pragma unroll
            for (int u2 = 0; u2 < 2; u2++) {
                int oc = ch*16 + u2*8 + og;
                size_t gi = (((size_t)b*128 + oc)*48 + py)*48 + px;
                out[gi] = o[ch*2+u2] + ob[oc] + feat[gi];
            }
        }
    }
}

// ============================================================================
extern "C" void kernel_launch(void* const* d_in, const int* in_sizes, int n_in,
                              void* d_out, int out_size) {
    const float* feat = (const float*)d_in[0];
    const float* lnw  = (const float*)d_in[1];
    const float* lnb  = (const float*)d_in[2];
    const float* qw   = (const float*)d_in[3];
    const float* qb   = (const float*)d_in[4];
    const float* kvw  = (const float*)d_in[5];
    const float* kvb  = (const float*)d_in[6];
    const float* ow   = (const float*)d_in[7];
    const float* ob   = (const float*)d_in[8];
    float* out = (float*)d_out;

    cudaFuncSetAttribute(k3_attn, cudaFuncAttributeMaxDynamicSharedMemorySize, 65536);

    k0_ln<<<1152, 256>>>(feat, lnw, lnb);
    k1_gemm<<<dim3(144, 3), 256>>>(qw, qb, kvw, kvb);
    k2_pool<<<2880, 256>>>();
    k3_attn<<<144, 512, 65536>>>(feat, kvb, ow, ob, out);
}

// round 10
// speedup vs baseline: 1.3347x; 1.0242x over previous
#include <cuda_runtime.h>
#include <cstdint>

// Problem constants
#define BB 4
#define HH 48
#define WW 48
#define CC 128

typedef unsigned long long u64;

// ---------------- scratch (device globals; no allocation allowed) ----------
__device__ float g_F [BB*HH*WW*CC];      // raw features, pixel-major
__device__ float g_FN[BB*HH*WW*CC];      // layernormed features, pixel-major
__device__ float g_Q [BB*HH*WW*CC];      // queries per pixel
__device__ float g_KV[BB*HH*WW*256];     // per-pixel KV projection (K|V)
__device__ float g_KVmid[BB*24*24*256];  // 2x2 pooled KV
__device__ float g_KVglo[BB*12*12*256];  // 4x4 pooled KV

__device__ __forceinline__ float ex2f(float x) {
    float r; asm("ex2.approx.f32 %0, %1;" : "=f"(r) : "f"(x)); return r;
}
__device__ __forceinline__ u64 ffma2(u64 a, u64 b, u64 c) {
    u64 d; asm("fma.rn.f32x2 %0,%1,%2,%3;" : "=l"(d) : "l"(a), "l"(b), "l"(c)); return d;
}
__device__ __forceinline__ u64 fmul2(u64 a, u64 b) {
    u64 d; asm("mul.rn.f32x2 %0,%1,%2;" : "=l"(d) : "l"(a), "l"(b)); return d;
}
__device__ __forceinline__ u64 pk2(float lo, float hi) {
    u64 d; asm("mov.b64 %0,{%1,%2};" : "=l"(d) : "f"(lo), "f"(hi)); return d;
}
__device__ __forceinline__ void up2(u64 v, float& lo, float& hi) {
    asm("mov.b64 {%0,%1},%2;" : "=f"(lo), "=f"(hi) : "l"(v));
}
__device__ __forceinline__ void cp16(uint32_t dst, const float* src) {
    asm volatile("cp.async.cg.shared.global [%0], [%1], 16;" :: "r"(dst), "l"(src));
}

// ============================================================================
// Kernel 0: transpose NCHW -> pixel-major + LayerNorm.  One warp per pixel.
// ============================================================================
__global__ void k0_ln(const float* __restrict__ feat,
                      const float* __restrict__ lnw,
                      const float* __restrict__ lnb) {
    int warp = (blockIdx.x * blockDim.x + threadIdx.x) >> 5;
    int lane = threadIdx.x & 31;
    if (warp >= BB*HH*WW) return;
    int b   = warp / (HH*WW);
    int rem = warp % (HH*WW);
    const float* src = feat + (size_t)b * CC * HH * WW + rem;

    float v[4];
    float s = 0.f, ss = 0.f;
#pragma unroll
    for (int i = 0; i < 4; i++) {
        int c = lane + 32*i;
        v[i] = src[(size_t)c * (HH*WW)];
        s  += v[i];
        ss += v[i]*v[i];
    }
#pragma unroll
    for (int o = 16; o; o >>= 1) {
        s  += __shfl_xor_sync(0xffffffffu, s,  o);
        ss += __shfl_xor_sync(0xffffffffu, ss, o);
    }
    float mean = s * (1.f/128.f);
    float var  = ss * (1.f/128.f) - mean*mean;
    float rstd = rsqrtf(var + 1e-5f);

    float* dF = g_F  + (size_t)warp * CC;
    float* dN = g_FN + (size_t)warp * CC;
#pragma unroll
    for (int i = 0; i < 4; i++) {
        int c = lane + 32*i;
        dF[c] = v[i];
        dN[c] = (v[i] - mean) * rstd * lnw[c] + lnb[c];
    }
}

// ============================================================================
// Kernel 1: fused GEMMs (Q / K / V projections).  Unchanged (known good).
// ============================================================================
#define MT 64
#define PADK 36

__global__ void k1_gemm(const float* __restrict__ qw, const float* __restrict__ qb,
                        const float* __restrict__ kvw, const float* __restrict__ kvb) {
    __shared__ float sA[MT][PADK];
    __shared__ float sB[128][PADK];

    int sub   = blockIdx.y;
    int mBase = blockIdx.x * MT;
    const float* A    = (sub == 0) ? g_FN : g_F;
    const float* Wm   = (sub == 0) ? qw : (kvw + (size_t)(sub-1)*128*128);
    const float* bias = (sub == 0) ? qb : (kvb + (sub-1)*128);

    int tid = threadIdx.x;
    int mg = tid & 15;
    int ng = tid >> 4;

    float acc[4][8];
#pragma unroll
    for (int m = 0; m < 4; m++)
#pragma unroll
        for (int n = 0; n < 8; n++) acc[m][n] = 0.f;

    for (int ck = 0; ck < 4; ck++) {
        __syncthreads();
#pragma unroll
        for (int i = 0; i < 2; i++) {
            int f = tid + i*256;
            int pix = f >> 3, kq = f & 7;
            float4 val = *(const float4*)(A + (size_t)(mBase+pix)*128 + ck*32 + kq*4);
            *(float4*)&sA[pix][kq*4] = val;
        }
#pragma unroll
        for (int i = 0; i < 4; i++) {
            int f = tid + i*256;
            int row = f >> 3, kq = f & 7;
            float4 val = *(const float4*)(Wm + (size_t)row*128 + ck*32 + kq*4);
            *(float4*)&sB[row][kq*4] = val;
        }
        __syncthreads();

#pragma unroll
        for (int k4 = 0; k4 < 8; k4++) {
            float4 a0 = *(const float4*)&sA[mg*4+0][k4*4];
            float4 a1 = *(const float4*)&sA[mg*4+1][k4*4];
            float4 a2 = *(const float4*)&sA[mg*4+2][k4*4];
            float4 a3 = *(const float4*)&sA[mg*4+3][k4*4];
#pragma unroll
            for (int n = 0; n < 8; n++) {
                float4 bv = *(const float4*)&sB[ng*8+n][k4*4];
                acc[0][n] += a0.x*bv.x + a0.y*bv.y + a0.z*bv.z + a0.w*bv.w;
                acc[1][n] += a1.x*bv.x + a1.y*bv.y + a1.z*bv.z + a1.w*bv.w;
                acc[2][n] += a2.x*bv.x + a2.y*bv.y + a2.z*bv.z + a2.w*bv.w;
                acc[3][n] += a3.x*bv.x + a3.y*bv.y + a3.z*bv.z + a3.w*bv.w;
            }
        }
    }

    float4 bv0 = *(const float4*)(bias + ng*8);
    float4 bv1 = *(const float4*)(bias + ng*8 + 4);
    int stride = (sub == 0) ? 128 : 256;
    float* base = (sub == 0) ? (g_Q + ng*8) : (g_KV + (sub-1)*128 + ng*8);
#pragma unroll
    for (int m = 0; m < 4; m++) {
        float* dst = base + (size_t)(mBase + mg*4 + m) * stride;
        float4 r0 = make_float4(acc[m][0]+bv0.x, acc[m][1]+bv0.y, acc[m][2]+bv0.z, acc[m][3]+bv0.w);
        float4 r1 = make_float4(acc[m][4]+bv1.x, acc[m][5]+bv1.y, acc[m][6]+bv1.z, acc[m][7]+bv1.w);
        *(float4*)dst       = r0;
        *((float4*)dst + 1) = r1;
    }
}

// ============================================================================
// Kernel 2: pooled KV.  Unchanged.
// ============================================================================
__global__ void k2_pool() {
    int t = blockIdx.x;
    int c = threadIdx.x;
    if (t < BB*576) {
        int b = t / 576, r = t % 576, my = r / 24, mx = r % 24;
        const float* base = g_KV + ((size_t)((b*48 + my*2)*48 + mx*2))*256 + c;
        float v = base[0] + base[256] + base[48*256] + base[48*256 + 256];
        g_KVmid[(size_t)t*256 + c] = v * 0.25f;
    } else {
        int t2 = t - BB*576;
        int b = t2 / 144, r = t2 % 144, gy = r / 12, gx = r % 12;
        float v = 0.f;
#pragma unroll
        for (int i = 0; i < 4; i++)
#pragma unroll
            for (int j = 0; j < 4; j++)
                v += g_KV[((size_t)((b*48 + gy*4 + i)*48 + gx*4 + j))*256 + c];
        g_KVglo[(size_t)t2*256 + c] = v * (1.f/16.f);
    }
}

// ============================================================================
// Kernel 3 v9 (= R9 + depth-4 ring, prefetch distance 2, ONE bar per step):
//   - ring = 4 x 32KB slots (2 tiles each), dynamic smem 128KB.
//   - per step: wait_group(own data) -> bar.sync(half) -> stage(s+2) ->
//     compute(s).  stage(s+2) writes slot (s+2)%4 which was last read by
//     compute(s-2), retired before the previous step's barrier.  Halves
//     stage/read disjoint rows of every slot, so inter-half drift is safe.
//   - epilogue: out-proj in 2 chunks of 64 weight rows (barriers 16 -> 4).
// ============================================================================
#define NSTEP 31     // 31 steps x 2 tiles = 62 (tile 61 = pad)

__global__ void __launch_bounds__(512, 1)
k3_attn(const float* __restrict__ feat, const float* __restrict__ kvb,
        const float* __restrict__ ow,   const float* __restrict__ ob,
        float* __restrict__ out) {
    extern __shared__ float ds[];    // 131072 B: ring[4][32][256]

    int cta = blockIdx.x;
    int b = cta / 36, g = cta % 36;
    int gy = g / 6, gx = g % 6;
    int tid  = threadIdx.x;
    int lane = tid & 31;
    int warp = tid >> 5;
    int h = warp & 7, th = warp >> 3;     // head, half
    int barid = 1 + th;

    int qg0 = lane, qg1 = lane + 32;
    int wgA = qg0 >> 4, wgB = qg1 >> 4;   // wgA in {0,1}, wgB in {2,3}

    const float SC = 0.25f * 1.4426950408889634f;
    u64 SC2 = pk2(SC, SC);

    // ---- load 2 queries (16 dims each), pre-scaled ----
    u64 q0[8], q1[8];
    {
        int qi = qg0 & 15;
        int wy = gy*2 + (wgA>>1), wx = gx*2 + (wgA&1);
        int py = wy*4 + (qi>>2), px = wx*4 + (qi&3);
        const longlong2* qp = (const longlong2*)(g_Q + ((size_t)((b*48+py)*48+px))*128 + h*16);
#pragma unroll
        for (int i = 0; i < 4; i++) {
            longlong2 t2 = qp[i];
            q0[2*i]   = fmul2((u64)t2.x, SC2);
            q0[2*i+1] = fmul2((u64)t2.y, SC2);
        }
    }
    {
        int qi = qg1 & 15;
        int wy = gy*2 + (wgB>>1), wx = gx*2 + (wgB&1);
        int py = wy*4 + (qi>>2), px = wx*4 + (qi&3);
        const longlong2* qp = (const longlong2*)(g_Q + ((size_t)((b*48+py)*48+px))*128 + h*16);
#pragma unroll
        for (int i = 0; i < 4; i++) {
            longlong2 t2 = qp[i];
            q1[2*i]   = fmul2((u64)t2.x, SC2);
            q1[2*i+1] = fmul2((u64)t2.y, SC2);
        }
    }

    u64 acc0[8], acc1[8];
#pragma unroll
    for (int i = 0; i < 8; i++) { acc0[i] = 0ull; acc1[i] = 0ull; }
    float ls0 = 0.f, ls1 = 0.f;

    // staging: each half's 256 threads stage its 8 consumed rows per tile.
    int idx   = tid & 255;
    int sub   = idx >> 4;
    int rowit = th*8 + (sub & 7);     // row-in-tile this half consumes
    int tsel  = sub >> 3;             // which tile of the pair
    int scol  = (idx & 15) * 16;

    auto stage = [&](int s) {
        int tt = 2*s + tsel;
        const float* src;
        if (tt < 16) {
            int wgl = tt >> 2, st = tt & 3;
            int id2 = st*16 + rowit;
            int y = (gy*2 + (wgl>>1))*4 + (id2>>3) - 2;
            int x = (gx*2 + (wgl&1))*4  + (id2&7)  - 2;
            src = ((unsigned)y < 48u && (unsigned)x < 48u)
                ? (g_KV + ((size_t)((b*48+y)*48+x))*256) : kvb;
        } else if (tt < 52) {
            src = g_KVmid + ((size_t)(b*576 + (tt-16)*16 + rowit))*256;
        } else if (tt < 61) {
            src = g_KVglo + ((size_t)(b*144 + (tt-52)*16 + rowit))*256;
        } else {
            src = kvb;                // pad tile (never computed)
        }
        uint32_t dst = (uint32_t)__cvta_generic_to_shared(
            ds + (s&3)*8192 + (tsel*16 + rowit)*256 + scol);
        cp16(dst,      src + scol);
        cp16(dst + 16, src + scol + 4);
        cp16(dst + 32, src + scol + 8);
        cp16(dst + 48, src + scol + 12);
        asm volatile("cp.async.commit_group;");
    };

    // per-tile compute (rows th*8..th*8+7)
    auto compute = [&](const float* kbase, int tt) {
        if (tt < 16) {
            int wgl = tt >> 2;
            if (wgl < 2) {
                u64 mb = pk2((wgA == wgl) ? 0.f : -1e30f, 0.f);
#pragma unroll
                for (int j = 0; j < 8; j++) {
                    const longlong2* kp = (const longlong2*)(kbase + j*256);
                    longlong2 a0 = kp[0], a1 = kp[1], a2 = kp[2], a3 = kp[3];
                    u64 d0 = ffma2(q0[0], (u64)a0.x, mb);
                    d0 = ffma2(q0[1], (u64)a0.y, d0);
                    d0 = ffma2(q0[2], (u64)a1.x, d0);
                    d0 = ffma2(q0[3], (u64)a1.y, d0);
                    d0 = ffma2(q0[4], (u64)a2.x, d0);
                    d0 = ffma2(q0[5], (u64)a2.y, d0);
                    d0 = ffma2(q0[6], (u64)a3.x, d0);
                    d0 = ffma2(q0[7], (u64)a3.y, d0);
                    float a, bb;
                    up2(d0, a, bb); float p0 = ex2f(a + bb);
                    ls0 += p0;
                    u64 P0 = pk2(p0, p0);
                    const longlong2* vp = (const longlong2*)(kbase + j*256 + 128);
                    longlong2 v0 = vp[0], v1 = vp[1], v2 = vp[2], v3 = vp[3];
                    acc0[0] = ffma2(P0, (u64)v0.x, acc0[0]);
                    acc0[1] = ffma2(P0, (u64)v0.y, acc0[1]);
                    acc0[2] = ffma2(P0, (u64)v1.x, acc0[2]);
                    acc0[3] = ffma2(P0, (u64)v1.y, acc0[3]);
                    acc0[4] = ffma2(P0, (u64)v2.x, acc0[4]);
                    acc0[5] = ffma2(P0, (u64)v2.y, acc0[5]);
                    acc0[6] = ffma2(P0, (u64)v3.x, acc0[6]);
                    acc0[7] = ffma2(P0, (u64)v3.y, acc0[7]);
                }
            } else {
                u64 mb = pk2((wgB == wgl) ? 0.f : -1e30f, 0.f);
#pragma unroll
                for (int j = 0; j < 8; j++) {
                    const longlong2* kp = (const longlong2*)(kbase + j*256);
                    longlong2 a0 = kp[0], a1 = kp[1], a2 = kp[2], a3 = kp[3];
                    u64 d1 = ffma2(q1[0], (u64)a0.x, mb);
                    d1 = ffma2(q1[1], (u64)a0.y, d1);
                    d1 = ffma2(q1[2], (u64)a1.x, d1);
                    d1 = ffma2(q1[3], (u64)a1.y, d1);
                    d1 = ffma2(q1[4], (u64)a2.x, d1);
                    d1 = ffma2(q1[5], (u64)a2.y, d1);
                    d1 = ffma2(q1[6], (u64)a3.x, d1);
                    d1 = ffma2(q1[7], (u64)a3.y, d1);
                    float a, bb;
                    up2(d1, a, bb); float p1 = ex2f(a + bb);
                    ls1 += p1;
                    u64 P1 = pk2(p1, p1);
                    const longlong2* vp = (const longlong2*)(kbase + j*256 + 128);
                    longlong2 v0 = vp[0], v1 = vp[1], v2 = vp[2], v3 = vp[3];
                    acc1[0] = ffma2(P1, (u64)v0.x, acc1[0]);
                    acc1[1] = ffma2(P1, (u64)v0.y, acc1[1]);
                    acc1[2] = ffma2(P1, (u64)v1.x, acc1[2]);
                    acc1[3] = ffma2(P1, (u64)v1.y, acc1[3]);
                    acc1[4] = ffma2(P1, (u64)v2.x, acc1[4]);
                    acc1[5] = ffma2(P1, (u64)v2.y, acc1[5]);
                    acc1[6] = ffma2(P1, (u64)v3.x, acc1[6]);
                    acc1[7] = ffma2(P1, (u64)v3.y, acc1[7]);
                }
            }
        } else {
#pragma unroll 4
            for (int j = 0; j < 8; j++) {
                const longlong2* kp = (const longlong2*)(kbase + j*256);
                longlong2 a0 = kp[0], a1 = kp[1], a2 = kp[2], a3 = kp[3];

                u64 d0 = fmul2(q0[0], (u64)a0.x);
                d0 = ffma2(q0[1], (u64)a0.y, d0);
                d0 = ffma2(q0[2], (u64)a1.x, d0);
                d0 = ffma2(q0[3], (u64)a1.y, d0);
                d0 = ffma2(q0[4], (u64)a2.x, d0);
                d0 = ffma2(q0[5], (u64)a2.y, d0);
                d0 = ffma2(q0[6], (u64)a3.x, d0);
                d0 = ffma2(q0[7], (u64)a3.y, d0);
                u64 d1 = fmul2(q1[0], (u64)a0.x);
                d1 = ffma2(q1[1], (u64)a0.y, d1);
                d1 = ffma2(q1[2], (u64)a1.x, d1);
                d1 = ffma2(q1[3], (u64)a1.y, d1);
                d1 = ffma2(q1[4], (u64)a2.x, d1);
                d1 = ffma2(q1[5], (u64)a2.y, d1);
                d1 = ffma2(q1[6], (u64)a3.x, d1);
                d1 = ffma2(q1[7], (u64)a3.y, d1);

                float a, bb;
                up2(d0, a, bb); float p0 = ex2f(a + bb);
                up2(d1, a, bb); float p1 = ex2f(a + bb);
                ls0 += p0; ls1 += p1;
                u64 P0 = pk2(p0, p0), P1 = pk2(p1, p1);

                const longlong2* vp = (const longlong2*)(kbase + j*256 + 128);
                longlong2 v0 = vp[0], v1 = vp[1], v2 = vp[2], v3 = vp[3];
                acc0[0] = ffma2(P0, (u64)v0.x, acc0[0]);
                acc0[1] = ffma2(P0, (u64)v0.y, acc0[1]);
                acc0[2] = ffma2(P0, (u64)v1.x, acc0[2]);
                acc0[3] = ffma2(P0, (u64)v1.y, acc0[3]);
                acc0[4] = ffma2(P0, (u64)v2.x, acc0[4]);
                acc0[5] = ffma2(P0, (u64)v2.y, acc0[5]);
                acc0[6] = ffma2(P0, (u64)v3.x, acc0[6]);
                acc0[7] = ffma2(P0, (u64)v3.y, acc0[7]);
                acc1[0] = ffma2(P1, (u64)v0.x, acc1[0]);
                acc1[1] = ffma2(P1, (u64)v0.y, acc1[1]);
                acc1[2] = ffma2(P1, (u64)v1.x, acc1[2]);
                acc1[3] = ffma2(P1, (u64)v1.y, acc1[3]);
                acc1[4] = ffma2(P1, (u64)v2.x, acc1[4]);
                acc1[5] = ffma2(P1, (u64)v2.y, acc1[5]);
                acc1[6] = ffma2(P1, (u64)v3.x, acc1[6]);
                acc1[7] = ffma2(P1, (u64)v3.y, acc1[7]);
            }
        }
    };

    // prologue: fill prefetch pipeline (groups 0 and 1)
    stage(0);
    stage(1);

    for (int s = 0; s < NSTEP; s++) {
        // own group s must have landed (only group s+1 may stay pending)
        if (s < NSTEP-1) {
            asm volatile("cp.async.wait_group 1;");
        } else {
            asm volatile("cp.async.wait_group 0;");
        }
        // half-mates: group-s data visible, compute(s-1) (and s-2) retired
        asm volatile("bar.sync %0, %1;" :: "r"(barid), "r"(256) : "memory");
        // prefetch slot (s+2)%4 — last read by compute(s-2), retired above
        if (s + 2 < NSTEP) stage(s+2);

        const float* buf = ds + (s&3)*8192;
        int t0 = 2*s;
        compute(buf + (th*8)*256 + h*16, t0);
        if (t0 + 1 < 61)
            compute(buf + (16 + th*8)*256 + h*16, t0 + 1);
    }

    // ---- full barrier: both halves done with the ring before reuse ----
    __syncthreads();

    // ------------------- merge halves, normalize, epilogue -----------------
    float* att = ds;                    // [64][132]
    float* lsm = ds + 64*132;           // [64][8]
    float* wsm = ds + 64*132 + 64*8;    // [64][132]

    if (th == 0) {
        float* r0 = &att[qg0*132 + h*16];
        float* r1 = &att[qg1*132 + h*16];
#pragma unroll
        for (int i = 0; i < 8; i++) {
            float a, bb;
            up2(acc0[i], a, bb); r0[2*i] = a; r0[2*i+1] = bb;
            up2(acc1[i], a, bb); r1[2*i] = a; r1[2*i+1] = bb;
        }
        lsm[qg0*8 + h] = ls0;
        lsm[qg1*8 + h] = ls1;
    }
    __syncthreads();
    if (th == 1) {
        float inv0 = 1.f / (lsm[qg0*8 + h] + ls0);
        float inv1 = 1.f / (lsm[qg1*8 + h] + ls1);
        float* r0 = &att[qg0*132 + h*16];
        float* r1 = &att[qg1*132 + h*16];
#pragma unroll
        for (int i = 0; i < 8; i++) {
            float a, bb;
            up2(acc0[i], a, bb);
            r0[2*i]   = (r0[2*i]   + a ) * inv0;
            r0[2*i+1] = (r0[2*i+1] + bb) * inv0;
            up2(acc1[i], a, bb);
            r1[2*i]   = (r1[2*i]   + a ) * inv1;
            r1[2*i+1] = (r1[2*i+1] + bb) * inv1;
        }
    }
    __syncthreads();

    // ---- out projection: 2 chunks of 64 weight rows ----
    // thread = (aqi = tid>>3, og = tid&7); per chunk computes 8 channels
    int aqi = tid >> 3, og = tid & 7;
    float o[16];
#pragma unroll 1
    for (int c2 = 0; c2 < 2; c2++) {
        // load 64x128 weight chunk: 2048 float4, 4 per thread
#pragma unroll
        for (int i = 0; i < 4; i++) {
            int f = tid + i*512;
            int row = f >> 5, quad = f & 31;
            *(float4*)&wsm[row*132 + quad*4] =
                *(const float4*)(ow + (size_t)(c2*64 + row)*128 + quad*4);
        }
        __syncthreads();

        u64 r[8];
#pragma unroll
        for (int u2 = 0; u2 < 8; u2++) r[u2] = 0ull;
#pragma unroll 4
        for (int k4 = 0; k4 < 32; k4++) {
            longlong2 av = *(const longlong2*)&att[aqi*132 + k4*4];
#pragma unroll
            for (int u2 = 0; u2 < 8; u2++) {
                longlong2 wv = *(const longlong2*)&wsm[(u2*8+og)*132 + k4*4];
                r[u2] = ffma2((u64)av.x, (u64)wv.x, r[u2]);
                r[u2] = ffma2((u64)av.y, (u64)wv.y, r[u2]);
            }
        }
#pragma unroll
        for (int u2 = 0; u2 < 8; u2++) {
            float a, bb;
            up2(r[u2], a, bb);
            o[c2*8 + u2] = a + bb;
        }
        __syncthreads();
    }

    // ---- residual add + NCHW scatter store ----
    {
        int qi = aqi & 15, wq = aqi >> 4;
        int wy = gy*2 + (wq>>1), wx = gx*2 + (wq&1);
        int py = wy*4 + (qi>>2), px = wx*4 + (qi&3);
#pragma unroll
        for (int c2 = 0; c2 < 2; c2++) {
#pragma unroll
            for (int u2 = 0; u2 < 8; u2++) {
                int oc = c2*64 + u2*8 + og;
                size_t gi = (((size_t)b*128 + oc)*48 + py)*48 + px;
                out[gi] = o[c2*8+u2] + ob[oc] + feat[gi];
            }
        }
    }
}

// ============================================================================
extern "C" void kernel_launch(void* const* d_in, const int* in_sizes, int n_in,
                              void* d_out, int out_size) {
    const float* feat = (const float*)d_in[0];
    const float* lnw  = (const float*)d_in[1];
    const float* lnb  = (const float*)d_in[2];
    const float* qw   = (const float*)d_in[3];
    const float* qb   = (const float*)d_in[4];
    const float* kvw  = (const float*)d_in[5];
    const float* kvb  = (const float*)d_in[6];
    const float* ow   = (const float*)d_in[7];
    const float* ob   = (const float*)d_in[8];
    float* out = (float*)d_out;

    cudaFuncSetAttribute(k3_attn, cudaFuncAttributeMaxDynamicSharedMemorySize, 131072);

    k0_ln<<<1152, 256>>>(feat, lnw, lnb);
    k1_gemm<<<dim3(144, 3), 256>>>(qw, qb, kvw, kvb);
    k2_pool<<<2880, 256>>>();
    k3_attn<<<144, 512, 131072>>>(feat, kvb, ow, ob, out);
}

// round 11
// speedup vs baseline: 1.6156x; 1.2105x over previous
#include <cuda_runtime.h>
#include <cuda_bf16.h>
#include <cstdint>

#define BB 4
#define HH 48
#define WW 48
#define CC 128

typedef unsigned int u32;
typedef unsigned long long u64;

// ---------------- scratch (device globals; no allocation allowed) ----------
__device__ float g_F [BB*HH*WW*CC];                 // raw features, pixel-major
__device__ float g_FN[BB*HH*WW*CC];                 // layernormed features
__device__ __nv_bfloat16 g_Qb   [BB*HH*WW*CC];      // queries, bf16, pre-scaled
__device__ __nv_bfloat16 g_KVh  [BB*HH*WW*256];     // per-pixel KV, bf16
__device__ __nv_bfloat16 g_KVmidh[BB*24*24*256];    // 2x2 pooled KV, bf16
__device__ __nv_bfloat16 g_KVgloh[BB*12*12*256];    // 4x4 pooled KV, bf16
__device__ __nv_bfloat16 g_kvbh [256];              // bias token, bf16

__device__ __forceinline__ float ex2f(float x) {
    float r; asm("ex2.approx.f32 %0, %1;" : "=f"(r) : "f"(x)); return r;
}
__device__ __forceinline__ u32 packbf(float lo, float hi) {
    u32 r; asm("cvt.rn.satfinite.bf16x2.f32 %0, %1, %2;" : "=r"(r) : "f"(hi), "f"(lo));
    return r;
}
__device__ __forceinline__ u64 ffma2(u64 a, u64 b, u64 c) {
    u64 d; asm("fma.rn.f32x2 %0,%1,%2,%3;" : "=l"(d) : "l"(a), "l"(b), "l"(c)); return d;
}
__device__ __forceinline__ void up2(u64 v, float& lo, float& hi) {
    asm("mov.b64 {%0,%1},%2;" : "=f"(lo), "=f"(hi) : "l"(v));
}
__device__ __forceinline__ void cp16(u32 dst, const void* src) {
    asm volatile("cp.async.cg.shared.global [%0], [%1], 16;" :: "r"(dst), "l"(src));
}
// D += A(bf16) * B(bf16), fp32 accum, m16n8k16 row.col
__device__ __forceinline__ void mma_bf16(float d[4], const u32 a[4], const u32 b[2]) {
    asm volatile(
        "mma.sync.aligned.m16n8k16.row.col.f32.bf16.bf16.f32 "
        "{%0,%1,%2,%3},{%4,%5,%6,%7},{%8,%9},{%0,%1,%2,%3};"
        : "+f"(d[0]), "+f"(d[1]), "+f"(d[2]), "+f"(d[3])
        : "r"(a[0]), "r"(a[1]), "r"(a[2]), "r"(a[3]), "r"(b[0]), "r"(b[1]));
}

// ============================================================================
// Kernel 0: transpose NCHW -> pixel-major + LayerNorm.  Unchanged.
// ============================================================================
__global__ void k0_ln(const float* __restrict__ feat,
                      const float* __restrict__ lnw,
                      const float* __restrict__ lnb) {
    int warp = (blockIdx.x * blockDim.x + threadIdx.x) >> 5;
    int lane = threadIdx.x & 31;
    if (warp >= BB*HH*WW) return;
    int b   = warp / (HH*WW);
    int rem = warp % (HH*WW);
    const float* src = feat + (size_t)b * CC * HH * WW + rem;

    float v[4];
    float s = 0.f, ss = 0.f;
#pragma unroll
    for (int i = 0; i < 4; i++) {
        int c = lane + 32*i;
        v[i] = src[(size_t)c * (HH*WW)];
        s  += v[i];
        ss += v[i]*v[i];
    }
#pragma unroll
    for (int o = 16; o; o >>= 1) {
        s  += __shfl_xor_sync(0xffffffffu, s,  o);
        ss += __shfl_xor_sync(0xffffffffu, ss, o);
    }
    float mean = s * (1.f/128.f);
    float var  = ss * (1.f/128.f) - mean*mean;
    float rstd = rsqrtf(var + 1e-5f);

    float* dF = g_F  + (size_t)warp * CC;
    float* dN = g_FN + (size_t)warp * CC;
#pragma unroll
    for (int i = 0; i < 4; i++) {
        int c = lane + 32*i;
        dF[c] = v[i];
        dN[c] = (v[i] - mean) * rstd * lnw[c] + lnb[c];
    }
}

// ============================================================================
// Kernel 1: fused GEMMs.  Same compute; epilogue now writes bf16
// (Q additionally pre-scaled by 0.25*log2(e)).
// ============================================================================
#define MT 64
#define PADK 36

__global__ void k1_gemm(const float* __restrict__ qw, const float* __restrict__ qb,
                        const float* __restrict__ kvw, const float* __restrict__ kvb) {
    __shared__ float sA[MT][PADK];
    __shared__ float sB[128][PADK];

    int sub   = blockIdx.y;
    int mBase = blockIdx.x * MT;
    const float* A    = (sub == 0) ? g_FN : g_F;
    const float* Wm   = (sub == 0) ? qw : (kvw + (size_t)(sub-1)*128*128);
    const float* bias = (sub == 0) ? qb : (kvb + (sub-1)*128);

    int tid = threadIdx.x;
    int mg = tid & 15;
    int ng = tid >> 4;

    float acc[4][8];
#pragma unroll
    for (int m = 0; m < 4; m++)
#pragma unroll
        for (int n = 0; n < 8; n++) acc[m][n] = 0.f;

    for (int ck = 0; ck < 4; ck++) {
        __syncthreads();
#pragma unroll
        for (int i = 0; i < 2; i++) {
            int f = tid + i*256;
            int pix = f >> 3, kq = f & 7;
            float4 val = *(const float4*)(A + (size_t)(mBase+pix)*128 + ck*32 + kq*4);
            *(float4*)&sA[pix][kq*4] = val;
        }
#pragma unroll
        for (int i = 0; i < 4; i++) {
            int f = tid + i*256;
            int row = f >> 3, kq = f & 7;
            float4 val = *(const float4*)(Wm + (size_t)row*128 + ck*32 + kq*4);
            *(float4*)&sB[row][kq*4] = val;
        }
        __syncthreads();

#pragma unroll
        for (int k4 = 0; k4 < 8; k4++) {
            float4 a0 = *(const float4*)&sA[mg*4+0][k4*4];
            float4 a1 = *(const float4*)&sA[mg*4+1][k4*4];
            float4 a2 = *(const float4*)&sA[mg*4+2][k4*4];
            float4 a3 = *(const float4*)&sA[mg*4+3][k4*4];
#pragma unroll
            for (int n = 0; n < 8; n++) {
                float4 bv = *(const float4*)&sB[ng*8+n][k4*4];
                acc[0][n] += a0.x*bv.x + a0.y*bv.y + a0.z*bv.z + a0.w*bv.w;
                acc[1][n] += a1.x*bv.x + a1.y*bv.y + a1.z*bv.z + a1.w*bv.w;
                acc[2][n] += a2.x*bv.x + a2.y*bv.y + a2.z*bv.z + a2.w*bv.w;
                acc[3][n] += a3.x*bv.x + a3.y*bv.y + a3.z*bv.z + a3.w*bv.w;
            }
        }
    }

    const float SC = 0.25f * 1.4426950408889634f;
    float bv[8];
#pragma unroll
    for (int n = 0; n < 8; n++) bv[n] = bias[ng*8 + n];

#pragma unroll
    for (int m = 0; m < 4; m++) {
        int row = mBase + mg*4 + m;
        float v[8];
#pragma unroll
        for (int n = 0; n < 8; n++) {
            v[n] = acc[m][n] + bv[n];
            if (sub == 0) v[n] *= SC;
        }
        uint4 pk;
        pk.x = packbf(v[0], v[1]);
        pk.y = packbf(v[2], v[3]);
        pk.z = packbf(v[4], v[5]);
        pk.w = packbf(v[6], v[7]);
        __nv_bfloat16* dst = (sub == 0)
            ? (g_Qb  + (size_t)row*128 + ng*8)
            : (g_KVh + (size_t)row*256 + (sub-1)*128 + ng*8);
        *(uint4*)dst = pk;
    }
}

// ============================================================================
// Kernel 2: pooled KV (bf16 in/out, fp32 accumulate) + bias-token conversion.
// ============================================================================
__global__ void k2_pool(const float* __restrict__ kvb) {
    int t = blockIdx.x;
    int c = threadIdx.x;
    if (t < BB*576) {
        int b = t / 576, r = t % 576, my = r / 24, mx = r % 24;
        const __nv_bfloat16* base = g_KVh + ((size_t)((b*48 + my*2)*48 + mx*2))*256 + c;
        float v = __bfloat162float(base[0]) + __bfloat162float(base[256])
                + __bfloat162float(base[48*256]) + __bfloat162float(base[48*256 + 256]);
        g_KVmidh[(size_t)t*256 + c] = __float2bfloat16(v * 0.25f);
    } else if (t < BB*576 + BB*144) {
        int t2 = t - BB*576;
        int b = t2 / 144, r = t2 % 144, gy = r / 12, gx = r % 12;
        float v = 0.f;
#pragma unroll
        for (int i = 0; i < 4; i++)
#pragma unroll
            for (int j = 0; j < 4; j++)
                v += __bfloat162float(
                    g_KVh[((size_t)((b*48 + gy*4 + i)*48 + gx*4 + j))*256 + c]);
        g_KVgloh[(size_t)t2*256 + c] = __float2bfloat16(v * (1.f/16.f));
    } else {
        g_kvbh[c] = __float2bfloat16(kvb[c]);
    }
}

// ============================================================================
// Kernel 3 v10: tensor-core (HMMA bf16) flash attention.
//   144 CTAs (2x2 window group), 512 threads = 16 warps = 8 heads x 2 q-halves.
//   Warp handles 32 queries (2 m16 tiles; m-tile == one window).
//   61 token tiles of 16, staged bf16 into depth-4 ring (2 tiles/step,
//   row stride 264 bf16 for conflict-free b-frag loads), prefetch dist 2.
//   QK: mma m16n8k16 (A=Q frags from gmem once, B=K via LDS.32).
//   softmax: exact (no max), ex2 on fp32 S frags; ls lane-partials.
//   PV: P frags packed bf16 from S, V b-frags via LDS.U16+combine.
//   Epilogue: shfl-reduce ls, normalize O frags -> att smem, then the
//   known-good out-projection + residual (R10 verbatim).
// ============================================================================
#define NSTEP 31
#define ROWB 264                    // bf16 elements per staged row (256 + 8 pad)
#define SLOTB (32*ROWB)             // bf16 per ring slot (2 tiles)
#define SMEMB (4*SLOTB*2)           // bytes: 67584

__global__ void __launch_bounds__(512, 1)
k3_attn(const float* __restrict__ feat, const float* __restrict__ ow,
        const float* __restrict__ ob,   float* __restrict__ out) {
    extern __shared__ float ds[];
    __nv_bfloat16* dsh = (__nv_bfloat16*)ds;

    int cta = blockIdx.x;
    int b = cta / 36, g = cta % 36;
    int gy = g / 6, gx = g % 6;
    int tid  = threadIdx.x;
    int lane = tid & 31;
    int warp = tid >> 5;
    int h = warp & 7, mh = warp >> 3;      // head, query-half (2 m-tiles)
    int t4 = lane & 3, g4 = lane >> 2;

    // ---- Q A-frags (once, from gmem bf16; already scaled) ----
    u32 aQ[2][4];
    {
        const u32* qp = (const u32*)g_Qb;
#pragma unroll
        for (int m = 0; m < 2; m++) {
            int wg = mh*2 + m;
            int wy = gy*2 + (wg>>1), wx = gx*2 + (wg&1);
            int qa = g4,     pya = wy*4 + (qa>>2), pxa = wx*4 + (qa&3);
            int qb2 = g4+8,  pyb = wy*4 + (qb2>>2), pxb = wx*4 + (qb2&3);
            size_t pa = (size_t)((b*48+pya)*48+pxa)*64 + h*8 + t4;
            size_t pb = (size_t)((b*48+pyb)*48+pxb)*64 + h*8 + t4;
            aQ[m][0] = qp[pa];     aQ[m][1] = qp[pb];
            aQ[m][2] = qp[pa+4];   aQ[m][3] = qp[pb+4];
        }
    }

    float o[2][2][4];
#pragma unroll
    for (int m = 0; m < 2; m++)
#pragma unroll
        for (int n = 0; n < 2; n++)
#pragma unroll
            for (int i = 0; i < 4; i++) o[m][n][i] = 0.f;
    float ls[2][2] = {{0.f,0.f},{0.f,0.f}};

    // ---- staging: 2 chunks of 16B per thread per step ----
    auto stage = [&](int s) {
#pragma unroll
        for (int c2 = 0; c2 < 2; c2++) {
            int flat = tid + c2*512;
            int tsel = flat >> 9;
            int row  = (flat >> 5) & 15;
            int ch   = flat & 31;
            int tt = 2*s + tsel;
            const char* src;
            if (tt < 16) {
                int wgl = tt >> 2, st = tt & 3;
                int id2 = st*16 + row;
                int y = (gy*2 + (wgl>>1))*4 + (id2>>3) - 2;
                int x = (gx*2 + (wgl&1))*4  + (id2&7)  - 2;
                src = ((unsigned)y < 48u && (unsigned)x < 48u)
                    ? (const char*)(g_KVh + ((size_t)((b*48+y)*48+x))*256)
                    : (const char*)g_kvbh;
            } else if (tt < 52) {
                src = (const char*)(g_KVmidh + ((size_t)(b*576 + (tt-16)*16 + row))*256);
            } else if (tt < 61) {
                src = (const char*)(g_KVgloh + ((size_t)(b*144 + (tt-52)*16 + row))*256);
            } else {
                src = (const char*)g_kvbh;
            }
            u32 dst = (u32)__cvta_generic_to_shared(
                dsh + (size_t)(s&3)*SLOTB + (tsel*16 + row)*ROWB) + ch*16;
            cp16(dst, src + ch*16);
        }
        asm volatile("cp.async.commit_group;");
    };

    // ---- per-tile tensor-core compute ----
    auto compute = [&](const __nv_bfloat16* tile, int tt) {
        int m0 = 0, m1 = 2;                 // m-tile range
        if (tt < 16) {
            int wgl = tt >> 2;
            if ((wgl >> 1) != mh) return;   // other half's window
            m0 = wgl & 1; m1 = m0 + 1;      // exactly one m-tile, no masks
        }
        // K b-frags (2 n-tiles)
        u32 bK[2][2];
#pragma unroll
        for (int n = 0; n < 2; n++) {
            const u32* kp = (const u32*)(tile + (n*8 + g4)*ROWB) + h*8 + t4;
            bK[n][0] = kp[0];
            bK[n][1] = kp[4];
        }
        // V b-frags (2 d-tiles)
        u32 bV[2][2];
#pragma unroll
        for (int vd = 0; vd < 2; vd++) {
            int col = 128 + h*16 + vd*8 + g4;
            u32 l0 = (u32)*(const unsigned short*)(tile + (2*t4  )*ROWB + col);
            u32 h0 = (u32)*(const unsigned short*)(tile + (2*t4+1)*ROWB + col);
            u32 l1 = (u32)*(const unsigned short*)(tile + (2*t4+8)*ROWB + col);
            u32 h1 = (u32)*(const unsigned short*)(tile + (2*t4+9)*ROWB + col);
            bV[vd][0] = l0 | (h0 << 16);
            bV[vd][1] = l1 | (h1 << 16);
        }
        for (int m = m0; m < m1; m++) {
            float S[2][4];
#pragma unroll
            for (int n = 0; n < 2; n++) {
#pragma unroll
                for (int i = 0; i < 4; i++) S[n][i] = 0.f;
                mma_bf16(S[n], aQ[m], bK[n]);
#pragma unroll
                for (int i = 0; i < 4; i++) S[n][i] = ex2f(S[n][i]);
                ls[m][0] += S[n][0] + S[n][1];
                ls[m][1] += S[n][2] + S[n][3];
            }
            u32 aP[4];
            aP[0] = packbf(S[0][0], S[0][1]);
            aP[1] = packbf(S[0][2], S[0][3]);
            aP[2] = packbf(S[1][0], S[1][1]);
            aP[3] = packbf(S[1][2], S[1][3]);
#pragma unroll
            for (int vd = 0; vd < 2; vd++)
                mma_bf16(o[m][vd], aP, bV[vd]);
        }
    };

    // ---- mainloop: depth-4 ring, prefetch distance 2 ----
    stage(0);
    stage(1);
    for (int s = 0; s < NSTEP; s++) {
        if (s < NSTEP-1) {
            asm volatile("cp.async.wait_group 1;");
        } else {
            asm volatile("cp.async.wait_group 0;");
        }
        __syncthreads();
        if (s + 2 < NSTEP) stage(s+2);

        const __nv_bfloat16* buf = dsh + (size_t)(s&3)*SLOTB;
        int t0 = 2*s;
        compute(buf, t0);
        if (t0 + 1 < 61) compute(buf + 16*ROWB, t0 + 1);
    }
    __syncthreads();

    // ---- reduce ls across the 4 lanes of each row group ----
#pragma unroll
    for (int m = 0; m < 2; m++)
#pragma unroll
        for (int r = 0; r < 2; r++) {
            float v = ls[m][r];
            v += __shfl_xor_sync(0xffffffffu, v, 1);
            v += __shfl_xor_sync(0xffffffffu, v, 2);
            ls[m][r] = v;
        }

    // ---- normalize O frags -> att smem ----
    float* att = ds;                    // [64][132]
    float* wsm = ds + 64*132;           // [64][132]
#pragma unroll
    for (int m = 0; m < 2; m++) {
        float inv0 = 1.f / ls[m][0];
        float inv1 = 1.f / ls[m][1];
        int r0 = mh*32 + m*16 + g4;
#pragma unroll
        for (int n = 0; n < 2; n++) {
            int col = h*16 + n*8 + 2*t4;
            *(float2*)&att[r0*132 + col]     = make_float2(o[m][n][0]*inv0, o[m][n][1]*inv0);
            *(float2*)&att[(r0+8)*132 + col] = make_float2(o[m][n][2]*inv1, o[m][n][3]*inv1);
        }
    }
    __syncthreads();

    // ---- out projection: 2 chunks of 64 weight rows (R10 verbatim) ----
    int aqi = tid >> 3, og = tid & 7;
    float ov[16];
#pragma unroll 1
    for (int c2 = 0; c2 < 2; c2++) {
#pragma unroll
        for (int i = 0; i < 4; i++) {
            int f = tid + i*512;
            int row = f >> 5, quad = f & 31;
            *(float4*)&wsm[row*132 + quad*4] =
                *(const float4*)(ow + (size_t)(c2*64 + row)*128 + quad*4);
        }
        __syncthreads();

        u64 r[8];
#pragma unroll
        for (int u2 = 0; u2 < 8; u2++) r[u2] = 0ull;
#pragma unroll 4
        for (int k4 = 0; k4 < 32; k4++) {
            longlong2 av = *(const longlong2*)&att[aqi*132 + k4*4];
#pragma unroll
            for (int u2 = 0; u2 < 8; u2++) {
                longlong2 wv = *(const longlong2*)&wsm[(u2*8+og)*132 + k4*4];
                r[u2] = ffma2((u64)av.x, (u64)wv.x, r[u2]);
                r[u2] = ffma2((u64)av.y, (u64)wv.y, r[u2]);
            }
        }
#pragma unroll
        for (int u2 = 0; u2 < 8; u2++) {
            float a, bb;
            up2(r[u2], a, bb);
            ov[c2*8 + u2] = a + bb;
        }
        __syncthreads();
    }

    // ---- residual add + NCHW scatter store ----
    {
        int qi = aqi & 15, wq = aqi >> 4;
        int wy = gy*2 + (wq>>1), wx = gx*2 + (wq&1);
        int py = wy*4 + (qi>>2), px = wx*4 + (qi&3);
#pragma unroll
        for (int c2 = 0; c2 < 2; c2++) {
#pragma unroll
            for (int u2 = 0; u2 < 8; u2++) {
                int oc = c2*64 + u2*8 + og;
                size_t gi = (((size_t)b*128 + oc)*48 + py)*48 + px;
                out[gi] = ov[c2*8+u2] + ob[oc] + feat[gi];
            }
        }
    }
}

// ============================================================================
extern "C" void kernel_launch(void* const* d_in, const int* in_sizes, int n_in,
                              void* d_out, int out_size) {
    const float* feat = (const float*)d_in[0];
    const float* lnw  = (const float*)d_in[1];
    const float* lnb  = (const float*)d_in[2];
    const float* qw   = (const float*)d_in[3];
    const float* qb   = (const float*)d_in[4];
    const float* kvw  = (const float*)d_in[5];
    const float* kvb  = (const float*)d_in[6];
    const float* ow   = (const float*)d_in[7];
    const float* ob   = (const float*)d_in[8];
    float* out = (float*)d_out;

    cudaFuncSetAttribute(k3_attn, cudaFuncAttributeMaxDynamicSharedMemorySize, SMEMB);

    k0_ln<<<1152, 256>>>(feat, lnw, lnb);
    k1_gemm<<<dim3(144, 3), 256>>>(qw, qb, kvw, kvb);
    k2_pool<<<2881, 256>>>(kvb);
    k3_attn<<<144, 512, SMEMB>>>(feat, ow, ob, out);
}